// round 13
// baseline (speedup 1.0000x reference)
#include <cuda_runtime.h>
#include <cuda_bf16.h>
#include <cuda_fp16.h>
#include <cstdint>

#define D_MODELX 1024
#define NUM_HEADSX 16
#define D_HEADX 64
#define BATCHX 4
#define SEQX 2048
#define M_TOK (BATCHX * SEQX)    // 8192
#define NZ (BATCHX * NUM_HEADSX) // 64

// ---- static device scratch ----
__device__ __nv_bfloat16 g_Qh[(size_t)M_TOK * D_MODELX];
__device__ __nv_bfloat16 g_Ql[(size_t)M_TOK * D_MODELX];
__device__ __nv_bfloat16 g_Kh[(size_t)M_TOK * D_MODELX];
__device__ __nv_bfloat16 g_Kl[(size_t)M_TOK * D_MODELX];
__device__ __half g_Vth[(size_t)M_TOK * D_MODELX];  // [Z][64][2048] fp16 hi
__device__ __half g_Vtl[(size_t)M_TOK * D_MODELX];  // [Z][64][2048] fp16 lo
__device__ float  g_O[(size_t)M_TOK * D_MODELX];
__device__ __half g_P[(size_t)NZ * SEQX * SEQX];    // 0.5 GiB fp16 exp(scores)
__device__ float  g_rinv[(size_t)NZ * SEQX];

__device__ __forceinline__ unsigned pack_bf2(float x, float y) {
    __nv_bfloat162 t = __floats2bfloat162_rn(x, y);
    return *reinterpret_cast<unsigned*>(&t);
}

__device__ __forceinline__ unsigned smem_u32(const void* p) {
    return (unsigned)__cvta_generic_to_shared(p);
}

#define LDSM_X4(r0, r1, r2, r3, addr)                                         \
    asm volatile("ldmatrix.sync.aligned.m8n8.x4.shared.b16 {%0,%1,%2,%3}, [%4];" \
        : "=r"(r0), "=r"(r1), "=r"(r2), "=r"(r3) : "r"(addr))

#define MMA_BF16(c, a0, a1, a2, a3, b0, b1)                                   \
    asm volatile(                                                             \
        "mma.sync.aligned.m16n8k16.row.col.f32.bf16.bf16.f32 "                \
        "{%0,%1,%2,%3},{%4,%5,%6,%7},{%8,%9},{%0,%1,%2,%3};"                  \
        : "+f"(c[0]), "+f"(c[1]), "+f"(c[2]), "+f"(c[3])                      \
        : "r"(a0), "r"(a1), "r"(a2), "r"(a3), "r"(b0), "r"(b1))

#define MMA_F16(c, a0, a1, a2, a3, b0, b1)                                    \
    asm volatile(                                                             \
        "mma.sync.aligned.m16n8k16.row.col.f32.f16.f16.f32 "                  \
        "{%0,%1,%2,%3},{%4,%5,%6,%7},{%8,%9},{%0,%1,%2,%3};"                  \
        : "+f"(c[0]), "+f"(c[1]), "+f"(c[2]), "+f"(c[3])                      \
        : "r"(a0), "r"(a1), "r"(a2), "r"(a3), "r"(b0), "r"(b1))

// ============================================================================
// Projection GEMM, 128x128x32 tile, 512 threads (16 warps 4x4), warp 32x32.
// fp32 in, bf16 hi/lo split in-loop, 3-pass MMA, ldmatrix fragments.
// MODE 0: fp32 out + bias (output projection)
// MODE 3: V projection, transposed fp16 hi/lo store into [Z][64][2048]
// MODE 5: Q/K projection, bf16 hi/lo out + bias
// ============================================================================
template <int MODE>
__global__ __launch_bounds__(512)
void proj_gemm(const float* __restrict__ A,
               const float* __restrict__ B,
               float* __restrict__ C,
               void* __restrict__ Chv, void* __restrict__ Clv,
               const float* __restrict__ bias)
{
    constexpr int BK = 32;
    constexpr int SA = 40;
    constexpr int LD = D_MODELX;

    __shared__ __align__(16) __nv_bfloat16 AsH[128 * SA];
    __shared__ __align__(16) __nv_bfloat16 AsL[128 * SA];
    __shared__ __align__(16) __nv_bfloat16 BsH[128 * SA];
    __shared__ __align__(16) __nv_bfloat16 BsL[128 * SA];

    const int tid  = threadIdx.x;
    const int m0   = blockIdx.y * 128;
    const int n0   = blockIdx.x * 128;
    const int warp = tid >> 5, lane = tid & 31;
    const int wm = (warp & 3) * 32;
    const int wn = (warp >> 2) * 32;
    const int gr = lane >> 2;
    const int gc = lane & 3;
    const int ti = lane >> 3, ri = lane & 7;

    unsigned aHb[2], aLb[2], bHb[2], bLb[2];
    #pragma unroll
    for (int mi = 0; mi < 2; mi++) {
        int row = wm + mi * 16 + (ti & 1) * 8 + ri;
        int col = (ti >> 1) * 8;
        aHb[mi] = smem_u32(&AsH[row * SA + col]);
        aLb[mi] = smem_u32(&AsL[row * SA + col]);
    }
    #pragma unroll
    for (int nip = 0; nip < 2; nip++) {
        int row = wn + (nip * 2 + (ti >> 1)) * 8 + ri;
        int col = (ti & 1) * 8;
        bHb[nip] = smem_u32(&BsH[row * SA + col]);
        bLb[nip] = smem_u32(&BsL[row * SA + col]);
    }

    float acc[2][4][4] = {};
    float4 ra[2], rb[2];

    {
        #pragma unroll
        for (int i = 0; i < 2; i++) {
            int idx = tid + i * 512, row = idx >> 3, c4 = idx & 7;
            ra[i] = *(const float4*)(A + (size_t)(m0 + row) * LD + c4 * 4);
            rb[i] = *(const float4*)(B + (size_t)(n0 + row) * LD + c4 * 4);
        }
    }

    const int niter = D_MODELX / BK;  // 32
    for (int it = 0; it < niter; ++it) {
        #pragma unroll
        for (int i = 0; i < 2; i++) {
            int idx = tid + i * 512, row = idx >> 3, c4 = idx & 7;
            {
                float v0 = ra[i].x, v1 = ra[i].y, v2 = ra[i].z, v3 = ra[i].w;
                float h0 = __bfloat162float(__float2bfloat16_rn(v0));
                float h1 = __bfloat162float(__float2bfloat16_rn(v1));
                float h2 = __bfloat162float(__float2bfloat16_rn(v2));
                float h3 = __bfloat162float(__float2bfloat16_rn(v3));
                uint2 H, L;
                H.x = pack_bf2(v0, v1); H.y = pack_bf2(v2, v3);
                L.x = pack_bf2(v0 - h0, v1 - h1); L.y = pack_bf2(v2 - h2, v3 - h3);
                *(uint2*)&AsH[row * SA + c4 * 4] = H;
                *(uint2*)&AsL[row * SA + c4 * 4] = L;
            }
            {
                float v0 = rb[i].x, v1 = rb[i].y, v2 = rb[i].z, v3 = rb[i].w;
                float h0 = __bfloat162float(__float2bfloat16_rn(v0));
                float h1 = __bfloat162float(__float2bfloat16_rn(v1));
                float h2 = __bfloat162float(__float2bfloat16_rn(v2));
                float h3 = __bfloat162float(__float2bfloat16_rn(v3));
                uint2 H, L;
                H.x = pack_bf2(v0, v1); H.y = pack_bf2(v2, v3);
                L.x = pack_bf2(v0 - h0, v1 - h1); L.y = pack_bf2(v2 - h2, v3 - h3);
                *(uint2*)&BsH[row * SA + c4 * 4] = H;
                *(uint2*)&BsL[row * SA + c4 * 4] = L;
            }
        }
        __syncthreads();

        if (it + 1 < niter) {
            int k0 = (it + 1) * BK;
            #pragma unroll
            for (int i = 0; i < 2; i++) {
                int idx = tid + i * 512, row = idx >> 3, c4 = idx & 7;
                ra[i] = *(const float4*)(A + (size_t)(m0 + row) * LD + k0 + c4 * 4);
                rb[i] = *(const float4*)(B + (size_t)(n0 + row) * LD + k0 + c4 * 4);
            }
        }

        #pragma unroll
        for (int ks = 0; ks < 2; ks++) {
            const int kb2 = ks * 32;
            unsigned aH[2][4], aL[2][4], bH[2][4], bL[2][4];
            #pragma unroll
            for (int mi = 0; mi < 2; mi++) {
                LDSM_X4(aH[mi][0], aH[mi][1], aH[mi][2], aH[mi][3], aHb[mi] + kb2);
                LDSM_X4(aL[mi][0], aL[mi][1], aL[mi][2], aL[mi][3], aLb[mi] + kb2);
            }
            #pragma unroll
            for (int nip = 0; nip < 2; nip++) {
                LDSM_X4(bH[nip][0], bH[nip][1], bH[nip][2], bH[nip][3], bHb[nip] + kb2);
                LDSM_X4(bL[nip][0], bL[nip][1], bL[nip][2], bL[nip][3], bLb[nip] + kb2);
            }
            #pragma unroll
            for (int mi = 0; mi < 2; mi++)
                #pragma unroll
                for (int nip = 0; nip < 2; nip++)
                    #pragma unroll
                    for (int hh = 0; hh < 2; hh++) {
                        int ni = nip * 2 + hh;
                        unsigned b0 = bH[nip][hh * 2], b1 = bH[nip][hh * 2 + 1];
                        unsigned l0 = bL[nip][hh * 2], l1 = bL[nip][hh * 2 + 1];
                        MMA_BF16(acc[mi][ni], aH[mi][0], aH[mi][1], aH[mi][2], aH[mi][3], b0, b1);
                        MMA_BF16(acc[mi][ni], aH[mi][0], aH[mi][1], aH[mi][2], aH[mi][3], l0, l1);
                        MMA_BF16(acc[mi][ni], aL[mi][0], aL[mi][1], aL[mi][2], aL[mi][3], b0, b1);
                    }
        }
        __syncthreads();
    }

    #pragma unroll
    for (int mi = 0; mi < 2; mi++)
        #pragma unroll
        for (int ni = 0; ni < 4; ni++) {
            int r = m0 + wm + mi * 16 + gr;
            int c = n0 + wn + ni * 8 + gc * 2;
            float* cc = acc[mi][ni];
            if (MODE == 3) {
                __half* Ch = (__half*)Chv;
                __half* Cl = (__half*)Clv;
                int b = r >> 11, s = r & 2047;
                int h = c >> 6, d = c & 63;
                float b0 = bias[c], b1 = bias[c + 1];
                float v00 = cc[0] + b0, v01 = cc[1] + b1;
                float v10 = cc[2] + b0, v11 = cc[3] + b1;
                size_t base = ((size_t)(b * 16 + h) * 64 + d) * 2048;
                __half h00 = __float2half_rn(v00);
                __half h01 = __float2half_rn(v01);
                __half h10 = __float2half_rn(v10);
                __half h11 = __float2half_rn(v11);
                Ch[base + s]            = h00;
                Ch[base + 2048 + s]     = h01;
                Ch[base + s + 8]        = h10;
                Ch[base + 2048 + s + 8] = h11;
                Cl[base + s]            = __float2half_rn(v00 - __half2float(h00));
                Cl[base + 2048 + s]     = __float2half_rn(v01 - __half2float(h01));
                Cl[base + s + 8]        = __float2half_rn(v10 - __half2float(h10));
                Cl[base + 2048 + s + 8] = __float2half_rn(v11 - __half2float(h11));
            } else if (MODE == 5) {
                __nv_bfloat16* Ch = (__nv_bfloat16*)Chv;
                __nv_bfloat16* Cl = (__nv_bfloat16*)Clv;
                float b0 = bias[c], b1 = bias[c + 1];
                float v00 = cc[0] + b0, v01 = cc[1] + b1;
                float v10 = cc[2] + b0, v11 = cc[3] + b1;
                float h00 = __bfloat162float(__float2bfloat16_rn(v00));
                float h01 = __bfloat162float(__float2bfloat16_rn(v01));
                float h10 = __bfloat162float(__float2bfloat16_rn(v10));
                float h11 = __bfloat162float(__float2bfloat16_rn(v11));
                size_t o0 = (size_t)r * LD + c;
                size_t o1 = (size_t)(r + 8) * LD + c;
                *(unsigned*)&Ch[o0] = pack_bf2(v00, v01);
                *(unsigned*)&Ch[o1] = pack_bf2(v10, v11);
                *(unsigned*)&Cl[o0] = pack_bf2(v00 - h00, v01 - h01);
                *(unsigned*)&Cl[o1] = pack_bf2(v10 - h10, v11 - h11);
            } else {
                float b0 = bias[c], b1 = bias[c + 1];
                float2 v0 = make_float2(cc[0] + b0, cc[1] + b1);
                float2 v1 = make_float2(cc[2] + b0, cc[3] + b1);
                *(float2*)&C[(size_t)r * LD + c]       = v0;
                *(float2*)&C[(size_t)(r + 8) * LD + c] = v1;
            }
        }
}

// ============================================================================
// Fused scores + softmax + AV (unchanged from R12).
// ============================================================================
#define OQH   0
#define OQL   18432
#define OKH   36864
#define OKL   55296
#define OPT   73728
#define OVH   108544
#define OVL   125952
#define OINV  143360
#define OPSUM 143872
#define FUSED_SMEM 144896
#define SAQ 72
#define SAP 136

__global__ void __launch_bounds__(256, 1)
fused_attn(const __nv_bfloat16* __restrict__ Qh, const __nv_bfloat16* __restrict__ Ql,
           const __nv_bfloat16* __restrict__ Kh, const __nv_bfloat16* __restrict__ Kl,
           const __half* __restrict__ Vh, const __half* __restrict__ Vl,
           __half* __restrict__ P, float* __restrict__ rinv,
           float* __restrict__ O)
{
    extern __shared__ char sm[];
    __nv_bfloat16* sQH = (__nv_bfloat16*)(sm + OQH);
    __nv_bfloat16* sQL = (__nv_bfloat16*)(sm + OQL);
    __nv_bfloat16* sKH = (__nv_bfloat16*)(sm + OKH);
    __nv_bfloat16* sKL = (__nv_bfloat16*)(sm + OKL);
    __half* sPT = (__half*)(sm + OPT);
    __half* sVH = (__half*)(sm + OVH);
    __half* sVL = (__half*)(sm + OVL);
    float* sInv  = (float*)(sm + OINV);
    float* sPsum = (float*)(sm + OPSUM);

    const int z = blockIdx.z, bb = z >> 4, hh_ = z & 15;
    const int m0 = blockIdx.x * 128;
    const size_t qoff = (size_t)bb * SEQX * D_MODELX + (size_t)hh_ * D_HEADX;
    Qh += qoff; Ql += qoff; Kh += qoff; Kl += qoff;
    Vh += (size_t)z * D_HEADX * SEQX;
    Vl += (size_t)z * D_HEADX * SEQX;
    P  += (size_t)z * SEQX * SEQX;
    rinv += (size_t)z * SEQX;
    O  += qoff;

    const int tid  = threadIdx.x;
    const int warp = tid >> 5, lane = tid & 31;
    const int wm = (warp & 3) * 32;
    const int wn = (warp >> 2) * 64;
    const int wd = (warp >> 2) * 32;
    const int gr = lane >> 2;
    const int gc = lane & 3;
    const int ti = lane >> 3, ri = lane & 7;

    #pragma unroll
    for (int i = 0; i < 4; i++) {
        int idx = tid + i * 256, row = idx >> 3, c8 = idx & 7;
        size_t oa = (size_t)(m0 + row) * D_MODELX + c8 * 8;
        *(uint4*)&sQH[row * SAQ + c8 * 8] = *(const uint4*)(Qh + oa);
        *(uint4*)&sQL[row * SAQ + c8 * 8] = *(const uint4*)(Ql + oa);
    }

    unsigned aHb[2], aLb[2], bHb[4], bLb[4], pab[2], vHb[2], vLb[2];
    #pragma unroll
    for (int mi = 0; mi < 2; mi++) {
        int row = wm + mi * 16 + (ti & 1) * 8 + ri;
        int col = (ti >> 1) * 8;
        aHb[mi] = smem_u32(&sQH[row * SAQ + col]);
        aLb[mi] = smem_u32(&sQL[row * SAQ + col]);
        pab[mi] = smem_u32(&sPT[row * SAP + col]);
    }
    #pragma unroll
    for (int nip = 0; nip < 4; nip++) {
        int row = wn + (nip * 2 + (ti >> 1)) * 8 + ri;
        int col = (ti & 1) * 8;
        bHb[nip] = smem_u32(&sKH[row * SAQ + col]);
        bLb[nip] = smem_u32(&sKL[row * SAQ + col]);
    }
    #pragma unroll
    for (int nip = 0; nip < 2; nip++) {
        int row = wd + (nip * 2 + (ti >> 1)) * 8 + ri;
        int col = (ti & 1) * 8;
        vHb[nip] = smem_u32(&sVH[row * SAP + col]);
        vLb[nip] = smem_u32(&sVL[row * SAP + col]);
    }

    float Oacc[2][4][4] = {};
    float rowsum[4] = {0.f, 0.f, 0.f, 0.f};

    for (int nb = 0; nb < 16; nb++) {
        const int n0 = nb * 128;
        __syncthreads();

        #pragma unroll
        for (int i = 0; i < 4; i++) {
            int idx = tid + i * 256, row = idx >> 3, c8 = idx & 7;
            size_t ob = (size_t)(n0 + row) * D_MODELX + c8 * 8;
            *(uint4*)&sKH[row * SAQ + c8 * 8] = *(const uint4*)(Kh + ob);
            *(uint4*)&sKL[row * SAQ + c8 * 8] = *(const uint4*)(Kl + ob);
        }
        #pragma unroll
        for (int i = 0; i < 4; i++) {
            int idx = tid + i * 256, row = idx >> 4, c16 = idx & 15;
            size_t ov = (size_t)row * SEQX + n0 + c16 * 8;
            *(uint4*)&sVH[row * SAP + c16 * 8] = *(const uint4*)(Vh + ov);
            *(uint4*)&sVL[row * SAP + c16 * 8] = *(const uint4*)(Vl + ov);
        }
        __syncthreads();

        float acc[2][8][4] = {};
        #pragma unroll
        for (int ks = 0; ks < 4; ks++) {
            const int kb2 = ks * 32;
            unsigned aH[2][4], aL[2][4], bH[4][4], bL[4][4];
            #pragma unroll
            for (int mi = 0; mi < 2; mi++) {
                LDSM_X4(aH[mi][0], aH[mi][1], aH[mi][2], aH[mi][3], aHb[mi] + kb2);
                LDSM_X4(aL[mi][0], aL[mi][1], aL[mi][2], aL[mi][3], aLb[mi] + kb2);
            }
            #pragma unroll
            for (int nip = 0; nip < 4; nip++) {
                LDSM_X4(bH[nip][0], bH[nip][1], bH[nip][2], bH[nip][3], bHb[nip] + kb2);
                LDSM_X4(bL[nip][0], bL[nip][1], bL[nip][2], bL[nip][3], bLb[nip] + kb2);
            }
            #pragma unroll
            for (int nip = 0; nip < 4; nip++)
                #pragma unroll
                for (int hh = 0; hh < 2; hh++) {
                    int ni = nip * 2 + hh;
                    unsigned b0 = bH[nip][hh * 2], b1 = bH[nip][hh * 2 + 1];
                    unsigned l0 = bL[nip][hh * 2], l1 = bL[nip][hh * 2 + 1];
                    #pragma unroll
                    for (int mi = 0; mi < 2; mi++) {
                        MMA_BF16(acc[mi][ni], aH[mi][0], aH[mi][1], aH[mi][2], aH[mi][3], b0, b1);
                        MMA_BF16(acc[mi][ni], aH[mi][0], aH[mi][1], aH[mi][2], aH[mi][3], l0, l1);
                        MMA_BF16(acc[mi][ni], aL[mi][0], aL[mi][1], aL[mi][2], aL[mi][3], b0, b1);
                    }
                }
        }

        #pragma unroll
        for (int mi = 0; mi < 2; mi++)
            #pragma unroll
            for (int ni = 0; ni < 8; ni++) {
                int rl = wm + mi * 16 + gr;
                int c  = wn + ni * 8 + gc * 2;
                float* cc = acc[mi][ni];
                float e0 = __expf(cc[0] * 0.125f);
                float e1 = __expf(cc[1] * 0.125f);
                float e2 = __expf(cc[2] * 0.125f);
                float e3 = __expf(cc[3] * 0.125f);
                __half2 h0 = __floats2half2_rn(e0, e1);
                __half2 h1 = __floats2half2_rn(e2, e3);
                __stcs((int*)&P[(size_t)(m0 + rl) * SEQX + n0 + c], *(int*)&h0);
                __stcs((int*)&P[(size_t)(m0 + rl + 8) * SEQX + n0 + c], *(int*)&h1);
                *(__half2*)&sPT[rl * SAP + c]       = h0;
                *(__half2*)&sPT[(rl + 8) * SAP + c] = h1;
                rowsum[mi * 2]     += e0 + e1;
                rowsum[mi * 2 + 1] += e2 + e3;
            }
        __syncthreads();

        #pragma unroll
        for (int ks = 0; ks < 8; ks++) {
            const int kb2 = ks * 32;
            unsigned a[2][4], vH[2][4], vL[2][4];
            #pragma unroll
            for (int mi = 0; mi < 2; mi++)
                LDSM_X4(a[mi][0], a[mi][1], a[mi][2], a[mi][3], pab[mi] + kb2);
            #pragma unroll
            for (int nip = 0; nip < 2; nip++) {
                LDSM_X4(vH[nip][0], vH[nip][1], vH[nip][2], vH[nip][3], vHb[nip] + kb2);
                LDSM_X4(vL[nip][0], vL[nip][1], vL[nip][2], vL[nip][3], vLb[nip] + kb2);
            }
            #pragma unroll
            for (int mi = 0; mi < 2; mi++)
                #pragma unroll
                for (int nip = 0; nip < 2; nip++)
                    #pragma unroll
                    for (int hh = 0; hh < 2; hh++) {
                        int ni = nip * 2 + hh;
                        MMA_F16(Oacc[mi][ni], a[mi][0], a[mi][1], a[mi][2], a[mi][3],
                                vH[nip][hh * 2], vH[nip][hh * 2 + 1]);
                        MMA_F16(Oacc[mi][ni], a[mi][0], a[mi][1], a[mi][2], a[mi][3],
                                vL[nip][hh * 2], vL[nip][hh * 2 + 1]);
                    }
        }
    }

    #pragma unroll
    for (int j = 0; j < 4; j++) {
        rowsum[j] += __shfl_xor_sync(0xffffffffu, rowsum[j], 1);
        rowsum[j] += __shfl_xor_sync(0xffffffffu, rowsum[j], 2);
    }
    const int wnh = warp >> 2;
    if (gc == 0) {
        sPsum[wnh * 128 + wm + gr]      = rowsum[0];
        sPsum[wnh * 128 + wm + 8 + gr]  = rowsum[1];
        sPsum[wnh * 128 + wm + 16 + gr] = rowsum[2];
        sPsum[wnh * 128 + wm + 24 + gr] = rowsum[3];
    }
    __syncthreads();
    if (tid < 128) {
        float inv = 1.0f / (sPsum[tid] + sPsum[128 + tid]);
        sInv[tid] = inv;
        rinv[m0 + tid] = inv;
    }
    __syncthreads();

    #pragma unroll
    for (int mi = 0; mi < 2; mi++)
        #pragma unroll
        for (int ni = 0; ni < 4; ni++) {
            int rl = wm + mi * 16 + gr;
            int c  = wd + ni * 8 + gc * 2;
            float inv0 = sInv[rl], inv1 = sInv[rl + 8];
            float* cc = Oacc[mi][ni];
            *(float2*)&O[(size_t)(m0 + rl) * D_MODELX + c] =
                make_float2(cc[0] * inv0, cc[1] * inv0);
            *(float2*)&O[(size_t)(m0 + rl + 8) * D_MODELX + c] =
                make_float2(cc[2] * inv1, cc[3] * inv1);
        }
}

// ============================================================================
// avg: barrier-free head average.
// ============================================================================
__global__ __launch_bounds__(256)
void avg_kernel(const __half* __restrict__ P, const float* __restrict__ rinv,
                float* __restrict__ avg)
{
    const int bq = blockIdx.x;
    const int t  = threadIdx.x;
    const int b  = bq >> 11;
    const int q  = bq & 2047;

    float acc[8] = {};

    #pragma unroll 4
    for (int h = 0; h < NUM_HEADSX; ++h) {
        const int z = b * 16 + h;
        float inv = rinv[(size_t)z * SEQX + q];
        const uint4* p4 = (const uint4*)(P + ((size_t)z * SEQX + q) * SEQX);
        uint4 u = __ldcs(p4 + t);
        float2 v0 = __half22float2(*reinterpret_cast<__half2*>(&u.x));
        float2 v1 = __half22float2(*reinterpret_cast<__half2*>(&u.y));
        float2 v2 = __half22float2(*reinterpret_cast<__half2*>(&u.z));
        float2 v3 = __half22float2(*reinterpret_cast<__half2*>(&u.w));
        acc[0] += v0.x * inv; acc[1] += v0.y * inv;
        acc[2] += v1.x * inv; acc[3] += v1.y * inv;
        acc[4] += v2.x * inv; acc[5] += v2.y * inv;
        acc[6] += v3.x * inv; acc[7] += v3.y * inv;
    }

    float* a = avg + (size_t)bq * SEQX + t * 8;
    float4 o0 = make_float4(acc[0] * (1.0f / NUM_HEADSX), acc[1] * (1.0f / NUM_HEADSX),
                            acc[2] * (1.0f / NUM_HEADSX), acc[3] * (1.0f / NUM_HEADSX));
    float4 o1 = make_float4(acc[4] * (1.0f / NUM_HEADSX), acc[5] * (1.0f / NUM_HEADSX),
                            acc[6] * (1.0f / NUM_HEADSX), acc[7] * (1.0f / NUM_HEADSX));
    __stcs((float4*)a, o0);
    __stcs((float4*)(a + 4), o1);
}

// ============================================================================
// launch
// ============================================================================
extern "C" void kernel_launch(void* const* d_in, const int* in_sizes, int n_in,
                              void* d_out, int out_size)
{
    const float* x_q = (const float*)d_in[0];
    const float* x_k = (const float*)d_in[1];
    const float* x_v = (const float*)d_in[2];
    const float* Wq  = (const float*)d_in[3];
    const float* bq  = (const float*)d_in[4];
    const float* Wk  = (const float*)d_in[5];
    const float* bk  = (const float*)d_in[6];
    const float* Wv  = (const float*)d_in[7];
    const float* bv  = (const float*)d_in[8];
    const float* Wo  = (const float*)d_in[9];
    const float* bo  = (const float*)d_in[10];

    float* out = (float*)d_out;
    float* avg = out + (size_t)M_TOK * D_MODELX;

    __nv_bfloat16 *Qh, *Ql, *Kh, *Kl;
    __half *Vth, *Vtl, *P;
    float *gO, *rinv;
    cudaGetSymbolAddress((void**)&Qh, g_Qh);
    cudaGetSymbolAddress((void**)&Ql, g_Ql);
    cudaGetSymbolAddress((void**)&Kh, g_Kh);
    cudaGetSymbolAddress((void**)&Kl, g_Kl);
    cudaGetSymbolAddress((void**)&Vth, g_Vth);
    cudaGetSymbolAddress((void**)&Vtl, g_Vtl);
    cudaGetSymbolAddress((void**)&gO, g_O);
    cudaGetSymbolAddress((void**)&P, g_P);
    cudaGetSymbolAddress((void**)&rinv, g_rinv);

    cudaFuncSetAttribute(fused_attn, cudaFuncAttributeMaxDynamicSharedMemorySize,
                         FUSED_SMEM);

    dim3 blk5(512);
    dim3 blk(256);
    dim3 gproj(D_MODELX / 128, M_TOK / 128, 1);  // (8, 64)

    // 1-3) projections: Q/K -> bf16 hi/lo, V -> transposed fp16 hi/lo
    proj_gemm<5><<<gproj, blk5>>>(x_q, Wq, nullptr, Qh, Ql, bq);
    proj_gemm<5><<<gproj, blk5>>>(x_k, Wk, nullptr, Kh, Kl, bk);
    proj_gemm<3><<<gproj, blk5>>>(x_v, Wv, nullptr, Vth, Vtl, bv);

    // 4) fused scores + softmax + AV -> P(exp), rinv, O
    dim3 gf(SEQX / 128, 1, NZ);                  // (16, 1, 64)
    fused_attn<<<gf, blk, FUSED_SMEM>>>(Qh, Ql, Kh, Kl, Vth, Vtl, P, rinv, gO);

    // 5) head-average (barrier-free)
    avg_kernel<<<M_TOK, blk>>>(P, rinv, avg);

    // 6) output projection (fp32 out)
    proj_gemm<0><<<gproj, blk5>>>(gO, Wo, out, nullptr, nullptr, bo);
}

// round 14
// speedup vs baseline: 1.1148x; 1.1148x over previous
#include <cuda_runtime.h>
#include <cuda_bf16.h>
#include <cuda_fp16.h>
#include <cstdint>

#define D_MODELX 1024
#define NUM_HEADSX 16
#define D_HEADX 64
#define BATCHX 4
#define SEQX 2048
#define M_TOK (BATCHX * SEQX)    // 8192
#define NZ (BATCHX * NUM_HEADSX) // 64

// ---- static device scratch ----
__device__ __nv_bfloat16 g_Qh[(size_t)M_TOK * D_MODELX];
__device__ __nv_bfloat16 g_Ql[(size_t)M_TOK * D_MODELX];
__device__ __nv_bfloat16 g_Kh[(size_t)M_TOK * D_MODELX];
__device__ __nv_bfloat16 g_Kl[(size_t)M_TOK * D_MODELX];
__device__ __half g_Vth[(size_t)M_TOK * D_MODELX];  // [Z][64][2048] fp16 hi
__device__ __half g_Vtl[(size_t)M_TOK * D_MODELX];  // [Z][64][2048] fp16 lo
__device__ float  g_O[(size_t)M_TOK * D_MODELX];
__device__ __half g_P[(size_t)NZ * SEQX * SEQX];    // 0.5 GiB fp16 exp(scores)
__device__ float  g_rinv[(size_t)NZ * SEQX];

__device__ __forceinline__ unsigned pack_bf2(float x, float y) {
    __nv_bfloat162 t = __floats2bfloat162_rn(x, y);
    return *reinterpret_cast<unsigned*>(&t);
}

__device__ __forceinline__ unsigned smem_u32(const void* p) {
    return (unsigned)__cvta_generic_to_shared(p);
}

#define LDSM_X4(r0, r1, r2, r3, addr)                                         \
    asm volatile("ldmatrix.sync.aligned.m8n8.x4.shared.b16 {%0,%1,%2,%3}, [%4];" \
        : "=r"(r0), "=r"(r1), "=r"(r2), "=r"(r3) : "r"(addr))

#define MMA_BF16(c, a0, a1, a2, a3, b0, b1)                                   \
    asm volatile(                                                             \
        "mma.sync.aligned.m16n8k16.row.col.f32.bf16.bf16.f32 "                \
        "{%0,%1,%2,%3},{%4,%5,%6,%7},{%8,%9},{%0,%1,%2,%3};"                  \
        : "+f"(c[0]), "+f"(c[1]), "+f"(c[2]), "+f"(c[3])                      \
        : "r"(a0), "r"(a1), "r"(a2), "r"(a3), "r"(b0), "r"(b1))

#define MMA_F16(c, a0, a1, a2, a3, b0, b1)                                    \
    asm volatile(                                                             \
        "mma.sync.aligned.m16n8k16.row.col.f32.f16.f16.f32 "                  \
        "{%0,%1,%2,%3},{%4,%5,%6,%7},{%8,%9},{%0,%1,%2,%3};"                  \
        : "+f"(c[0]), "+f"(c[1]), "+f"(c[2]), "+f"(c[3])                      \
        : "r"(a0), "r"(a1), "r"(a2), "r"(a3), "r"(b0), "r"(b1))

#define CP_ASYNC16(dst, src)                                                  \
    asm volatile("cp.async.cg.shared.global [%0], [%1], 16;"                  \
        :: "r"(dst), "l"(src) : "memory")
#define CP_COMMIT() asm volatile("cp.async.commit_group;" ::: "memory")
#define CP_WAIT_ALL() asm volatile("cp.async.wait_group 0;" ::: "memory")

// ============================================================================
// NT bf16-split MMA GEMM (fp32 in, split in-kernel): C = A @ B^T + bias
// (R12 version — 128x64x32, 256 threads)
// MODE 0: fp32 out + bias; MODE 3: V proj transposed fp16 hi/lo;
// MODE 5: Q/K proj bf16 hi/lo + bias
// ============================================================================
template <int MODE>
__global__ __launch_bounds__(256)
void mma_gemm(const float* __restrict__ A,
              const float* __restrict__ B,
              float* __restrict__ C,
              void* __restrict__ Chv, void* __restrict__ Clv,
              int lda, int ldb, int ldc,
              int K, const float* __restrict__ bias)
{
    constexpr int BM = 128, BN = 64, BK = 32;
    constexpr int SA = 40;

    __shared__ __align__(16) __nv_bfloat16 AsH[BM * SA];
    __shared__ __align__(16) __nv_bfloat16 AsL[BM * SA];
    __shared__ __align__(16) __nv_bfloat16 BsH[BN * SA];
    __shared__ __align__(16) __nv_bfloat16 BsL[BN * SA];

    const int tid  = threadIdx.x;
    const int m0   = blockIdx.y * BM;
    const int n0   = blockIdx.x * BN;
    const int warp = tid >> 5, lane = tid & 31;
    const int wm = (warp & 3) * 32;
    const int wn = (warp >> 2) * 32;
    const int gr = lane >> 2;
    const int gc = lane & 3;
    const int ti = lane >> 3, ri = lane & 7;

    unsigned aHb[2], aLb[2], bHb[2], bLb[2];
    #pragma unroll
    for (int mi = 0; mi < 2; mi++) {
        int row = wm + mi * 16 + (ti & 1) * 8 + ri;
        int col = (ti >> 1) * 8;
        aHb[mi] = smem_u32(&AsH[row * SA + col]);
        aLb[mi] = smem_u32(&AsL[row * SA + col]);
    }
    #pragma unroll
    for (int nip = 0; nip < 2; nip++) {
        int row = wn + (nip * 2 + (ti >> 1)) * 8 + ri;
        int col = (ti & 1) * 8;
        bHb[nip] = smem_u32(&BsH[row * SA + col]);
        bLb[nip] = smem_u32(&BsL[row * SA + col]);
    }

    float acc[2][4][4] = {};
    float4 ra[4], rb[2];

    {
        #pragma unroll
        for (int i = 0; i < 4; i++) {
            int idx = tid + i * 256, row = idx >> 3, c4 = idx & 7;
            ra[i] = *(const float4*)(A + (size_t)(m0 + row) * lda + c4 * 4);
        }
        #pragma unroll
        for (int i = 0; i < 2; i++) {
            int idx = tid + i * 256, row = idx >> 3, c4 = idx & 7;
            rb[i] = *(const float4*)(B + (size_t)(n0 + row) * ldb + c4 * 4);
        }
    }

    const int niter = K / BK;
    for (int it = 0; it < niter; ++it) {
        #pragma unroll
        for (int i = 0; i < 4; i++) {
            int idx = tid + i * 256, row = idx >> 3, c4 = idx & 7;
            float v0 = ra[i].x, v1 = ra[i].y, v2 = ra[i].z, v3 = ra[i].w;
            float h0 = __bfloat162float(__float2bfloat16_rn(v0));
            float h1 = __bfloat162float(__float2bfloat16_rn(v1));
            float h2 = __bfloat162float(__float2bfloat16_rn(v2));
            float h3 = __bfloat162float(__float2bfloat16_rn(v3));
            uint2 H, L;
            H.x = pack_bf2(v0, v1); H.y = pack_bf2(v2, v3);
            L.x = pack_bf2(v0 - h0, v1 - h1); L.y = pack_bf2(v2 - h2, v3 - h3);
            *(uint2*)&AsH[row * SA + c4 * 4] = H;
            *(uint2*)&AsL[row * SA + c4 * 4] = L;
        }
        #pragma unroll
        for (int i = 0; i < 2; i++) {
            int idx = tid + i * 256, row = idx >> 3, c4 = idx & 7;
            float v0 = rb[i].x, v1 = rb[i].y, v2 = rb[i].z, v3 = rb[i].w;
            float h0 = __bfloat162float(__float2bfloat16_rn(v0));
            float h1 = __bfloat162float(__float2bfloat16_rn(v1));
            float h2 = __bfloat162float(__float2bfloat16_rn(v2));
            float h3 = __bfloat162float(__float2bfloat16_rn(v3));
            uint2 H, L;
            H.x = pack_bf2(v0, v1); H.y = pack_bf2(v2, v3);
            L.x = pack_bf2(v0 - h0, v1 - h1); L.y = pack_bf2(v2 - h2, v3 - h3);
            *(uint2*)&BsH[row * SA + c4 * 4] = H;
            *(uint2*)&BsL[row * SA + c4 * 4] = L;
        }
        __syncthreads();

        if (it + 1 < niter) {
            int k0 = (it + 1) * BK;
            #pragma unroll
            for (int i = 0; i < 4; i++) {
                int idx = tid + i * 256, row = idx >> 3, c4 = idx & 7;
                ra[i] = *(const float4*)(A + (size_t)(m0 + row) * lda + k0 + c4 * 4);
            }
            #pragma unroll
            for (int i = 0; i < 2; i++) {
                int idx = tid + i * 256, row = idx >> 3, c4 = idx & 7;
                rb[i] = *(const float4*)(B + (size_t)(n0 + row) * ldb + k0 + c4 * 4);
            }
        }

        #pragma unroll
        for (int ks = 0; ks < 2; ks++) {
            const int kb2 = ks * 32;
            unsigned aH[2][4], aL[2][4], bH[2][4], bL[2][4];
            #pragma unroll
            for (int mi = 0; mi < 2; mi++) {
                LDSM_X4(aH[mi][0], aH[mi][1], aH[mi][2], aH[mi][3], aHb[mi] + kb2);
                LDSM_X4(aL[mi][0], aL[mi][1], aL[mi][2], aL[mi][3], aLb[mi] + kb2);
            }
            #pragma unroll
            for (int nip = 0; nip < 2; nip++) {
                LDSM_X4(bH[nip][0], bH[nip][1], bH[nip][2], bH[nip][3], bHb[nip] + kb2);
                LDSM_X4(bL[nip][0], bL[nip][1], bL[nip][2], bL[nip][3], bLb[nip] + kb2);
            }
            #pragma unroll
            for (int mi = 0; mi < 2; mi++)
                #pragma unroll
                for (int nip = 0; nip < 2; nip++)
                    #pragma unroll
                    for (int hh = 0; hh < 2; hh++) {
                        int ni = nip * 2 + hh;
                        unsigned b0 = bH[nip][hh * 2], b1 = bH[nip][hh * 2 + 1];
                        unsigned l0 = bL[nip][hh * 2], l1 = bL[nip][hh * 2 + 1];
                        MMA_BF16(acc[mi][ni], aH[mi][0], aH[mi][1], aH[mi][2], aH[mi][3], b0, b1);
                        MMA_BF16(acc[mi][ni], aH[mi][0], aH[mi][1], aH[mi][2], aH[mi][3], l0, l1);
                        MMA_BF16(acc[mi][ni], aL[mi][0], aL[mi][1], aL[mi][2], aL[mi][3], b0, b1);
                    }
        }
        __syncthreads();
    }

    #pragma unroll
    for (int mi = 0; mi < 2; mi++)
        #pragma unroll
        for (int ni = 0; ni < 4; ni++) {
            int r = m0 + wm + mi * 16 + gr;
            int c = n0 + wn + ni * 8 + gc * 2;
            float* cc = acc[mi][ni];
            if (MODE == 3) {
                __half* Ch = (__half*)Chv;
                __half* Cl = (__half*)Clv;
                int b = r >> 11, s = r & 2047;
                int h = c >> 6, d = c & 63;
                float b0 = bias[c], b1 = bias[c + 1];
                float v00 = cc[0] + b0, v01 = cc[1] + b1;
                float v10 = cc[2] + b0, v11 = cc[3] + b1;
                size_t base = ((size_t)(b * 16 + h) * 64 + d) * 2048;
                __half h00 = __float2half_rn(v00);
                __half h01 = __float2half_rn(v01);
                __half h10 = __float2half_rn(v10);
                __half h11 = __float2half_rn(v11);
                Ch[base + s]            = h00;
                Ch[base + 2048 + s]     = h01;
                Ch[base + s + 8]        = h10;
                Ch[base + 2048 + s + 8] = h11;
                Cl[base + s]            = __float2half_rn(v00 - __half2float(h00));
                Cl[base + 2048 + s]     = __float2half_rn(v01 - __half2float(h01));
                Cl[base + s + 8]        = __float2half_rn(v10 - __half2float(h10));
                Cl[base + 2048 + s + 8] = __float2half_rn(v11 - __half2float(h11));
            } else if (MODE == 5) {
                __nv_bfloat16* Ch = (__nv_bfloat16*)Chv;
                __nv_bfloat16* Cl = (__nv_bfloat16*)Clv;
                float b0 = bias[c], b1 = bias[c + 1];
                float v00 = cc[0] + b0, v01 = cc[1] + b1;
                float v10 = cc[2] + b0, v11 = cc[3] + b1;
                float h00 = __bfloat162float(__float2bfloat16_rn(v00));
                float h01 = __bfloat162float(__float2bfloat16_rn(v01));
                float h10 = __bfloat162float(__float2bfloat16_rn(v10));
                float h11 = __bfloat162float(__float2bfloat16_rn(v11));
                size_t o0 = (size_t)r * ldc + c;
                size_t o1 = (size_t)(r + 8) * ldc + c;
                *(unsigned*)&Ch[o0] = pack_bf2(v00, v01);
                *(unsigned*)&Ch[o1] = pack_bf2(v10, v11);
                *(unsigned*)&Cl[o0] = pack_bf2(v00 - h00, v01 - h01);
                *(unsigned*)&Cl[o1] = pack_bf2(v10 - h10, v11 - h11);
            } else {
                float b0 = 0.f, b1 = 0.f;
                if (bias) { b0 = bias[c]; b1 = bias[c + 1]; }
                float2 v0 = make_float2(cc[0] + b0, cc[1] + b1);
                float2 v1 = make_float2(cc[2] + b0, cc[3] + b1);
                *(float2*)&C[(size_t)r * ldc + c]       = v0;
                *(float2*)&C[(size_t)(r + 8) * ldc + c] = v1;
            }
        }
}

// ============================================================================
// Fused scores + softmax + AV, cp.async double-buffered K/V.
// One block per (z, 128-row m-tile), 256 threads. smem ~217 KB.
// ============================================================================
#define OQH   0
#define OQL   18432
#define OKH0  36864
#define OKH1  55296
#define OKL0  73728
#define OKL1  92160
#define OVH0  110592
#define OVH1  128000
#define OVL0  145408
#define OVL1  162816
#define OPT   180224
#define OINV  215040
#define OPSUM 215552
#define FUSED_SMEM 216576
#define KBUF_STRIDE 18432
#define VBUF_STRIDE 17408
#define SAQ 72
#define SAP 136

__global__ void __launch_bounds__(256, 1)
fused_attn(const __nv_bfloat16* __restrict__ Qh, const __nv_bfloat16* __restrict__ Ql,
           const __nv_bfloat16* __restrict__ Kh, const __nv_bfloat16* __restrict__ Kl,
           const __half* __restrict__ Vh, const __half* __restrict__ Vl,
           __half* __restrict__ P, float* __restrict__ rinv,
           float* __restrict__ O)
{
    extern __shared__ char sm[];
    __nv_bfloat16* sQH = (__nv_bfloat16*)(sm + OQH);
    __nv_bfloat16* sQL = (__nv_bfloat16*)(sm + OQL);
    __half* sPT = (__half*)(sm + OPT);
    float* sInv  = (float*)(sm + OINV);
    float* sPsum = (float*)(sm + OPSUM);

    const unsigned kh0 = smem_u32(sm + OKH0);
    const unsigned kl0 = smem_u32(sm + OKL0);
    const unsigned vh0 = smem_u32(sm + OVH0);
    const unsigned vl0 = smem_u32(sm + OVL0);

    const int z = blockIdx.z, bb = z >> 4, hh_ = z & 15;
    const int m0 = blockIdx.x * 128;
    const size_t qoff = (size_t)bb * SEQX * D_MODELX + (size_t)hh_ * D_HEADX;
    Qh += qoff; Ql += qoff; Kh += qoff; Kl += qoff;
    Vh += (size_t)z * D_HEADX * SEQX;
    Vl += (size_t)z * D_HEADX * SEQX;
    P  += (size_t)z * SEQX * SEQX;
    rinv += (size_t)z * SEQX;
    O  += qoff;

    const int tid  = threadIdx.x;
    const int warp = tid >> 5, lane = tid & 31;
    const int wm = (warp & 3) * 32;
    const int wn = (warp >> 2) * 64;
    const int wd = (warp >> 2) * 32;
    const int gr = lane >> 2;
    const int gc = lane & 3;
    const int ti = lane >> 3, ri = lane & 7;

    // per-thread load coordinates (reused every iteration)
    const int krow = tid >> 1;               // 2 threads/row? no: see below
    // K tile: 128 rows x 64 bf16 (128B/row) -> 8 chunks of 16B per row;
    // 256 threads x 4 chunks: idx = tid + i*256, row = idx>>3, c8 = idx&7
    // V tile: 64 rows x 128 halfs (256B/row) -> 16 chunks/row;
    // idx = tid + i*256, row = idx>>4, c16 = idx&15
    (void)krow;

    // ---- load Q tile once (regular loads) ----
    #pragma unroll
    for (int i = 0; i < 4; i++) {
        int idx = tid + i * 256, row = idx >> 3, c8 = idx & 7;
        size_t oa = (size_t)(m0 + row) * D_MODELX + c8 * 8;
        *(uint4*)&sQH[row * SAQ + c8 * 8] = *(const uint4*)(Qh + oa);
        *(uint4*)&sQL[row * SAQ + c8 * 8] = *(const uint4*)(Ql + oa);
    }

    // ---- prefetch K/V tile 0 into buffer 0 ----
    {
        const int n0 = 0;
        #pragma unroll
        for (int i = 0; i < 4; i++) {
            int idx = tid + i * 256, row = idx >> 3, c8 = idx & 7;
            unsigned so = (unsigned)(row * SAQ + c8 * 8) * 2;
            const __nv_bfloat16* gk = Kh + (size_t)(n0 + row) * D_MODELX + c8 * 8;
            const __nv_bfloat16* gl = Kl + (size_t)(n0 + row) * D_MODELX + c8 * 8;
            CP_ASYNC16(kh0 + so, gk);
            CP_ASYNC16(kl0 + so, gl);
        }
        #pragma unroll
        for (int i = 0; i < 4; i++) {
            int idx = tid + i * 256, row = idx >> 4, c16 = idx & 15;
            unsigned so = (unsigned)(row * SAP + c16 * 8) * 2;
            const __half* gvh = Vh + (size_t)row * SEQX + n0 + c16 * 8;
            const __half* gvl = Vl + (size_t)row * SEQX + n0 + c16 * 8;
            CP_ASYNC16(vh0 + so, gvh);
            CP_ASYNC16(vl0 + so, gvl);
        }
        CP_COMMIT();
    }

    // fragment bases (buffer 0; add buffer stride at use)
    unsigned aHb[2], aLb[2], bHb[4], bLb[4], pab[2], vHb[2], vLb[2];
    #pragma unroll
    for (int mi = 0; mi < 2; mi++) {
        int row = wm + mi * 16 + (ti & 1) * 8 + ri;
        int col = (ti >> 1) * 8;
        aHb[mi] = smem_u32(&sQH[row * SAQ + col]);
        aLb[mi] = smem_u32(&sQL[row * SAQ + col]);
        pab[mi] = smem_u32(&sPT[row * SAP + col]);
    }
    #pragma unroll
    for (int nip = 0; nip < 4; nip++) {
        int row = wn + (nip * 2 + (ti >> 1)) * 8 + ri;
        int col = (ti & 1) * 8;
        bHb[nip] = kh0 + (unsigned)(row * SAQ + col) * 2;
        bLb[nip] = kl0 + (unsigned)(row * SAQ + col) * 2;
    }
    #pragma unroll
    for (int nip = 0; nip < 2; nip++) {
        int row = wd + (nip * 2 + (ti >> 1)) * 8 + ri;
        int col = (ti & 1) * 8;
        vHb[nip] = vh0 + (unsigned)(row * SAP + col) * 2;
        vLb[nip] = vl0 + (unsigned)(row * SAP + col) * 2;
    }

    float Oacc[2][4][4] = {};
    float rowsum[4] = {0.f, 0.f, 0.f, 0.f};

    for (int nb = 0; nb < 16; nb++) {
        const int n0 = nb * 128;
        const unsigned kofs = (unsigned)(nb & 1) * KBUF_STRIDE;
        const unsigned vofs = (unsigned)(nb & 1) * VBUF_STRIDE;

        CP_WAIT_ALL();
        __syncthreads();   // cur buffers ready; all warps past previous AV

        // ---- prefetch next tile into the other buffer ----
        if (nb + 1 < 16) {
            const int n1 = n0 + 128;
            const unsigned kn = (unsigned)((nb + 1) & 1) * KBUF_STRIDE;
            const unsigned vn = (unsigned)((nb + 1) & 1) * VBUF_STRIDE;
            #pragma unroll
            for (int i = 0; i < 4; i++) {
                int idx = tid + i * 256, row = idx >> 3, c8 = idx & 7;
                unsigned so = (unsigned)(row * SAQ + c8 * 8) * 2;
                const __nv_bfloat16* gk = Kh + (size_t)(n1 + row) * D_MODELX + c8 * 8;
                const __nv_bfloat16* gl = Kl + (size_t)(n1 + row) * D_MODELX + c8 * 8;
                CP_ASYNC16(kh0 + kn + so, gk);
                CP_ASYNC16(kl0 + kn + so, gl);
            }
            #pragma unroll
            for (int i = 0; i < 4; i++) {
                int idx = tid + i * 256, row = idx >> 4, c16 = idx & 15;
                unsigned so = (unsigned)(row * SAP + c16 * 8) * 2;
                const __half* gvh = Vh + (size_t)row * SEQX + n1 + c16 * 8;
                const __half* gvl = Vl + (size_t)row * SEQX + n1 + c16 * 8;
                CP_ASYNC16(vh0 + vn + so, gvh);
                CP_ASYNC16(vl0 + vn + so, gvl);
            }
            CP_COMMIT();
        }

        // ---- scores: S = QK^T, 3-pass bf16 ----
        float acc[2][8][4] = {};
        #pragma unroll
        for (int ks = 0; ks < 4; ks++) {
            const int kb2 = ks * 32;
            unsigned aH[2][4], aL[2][4], bH[4][4], bL[4][4];
            #pragma unroll
            for (int mi = 0; mi < 2; mi++) {
                LDSM_X4(aH[mi][0], aH[mi][1], aH[mi][2], aH[mi][3], aHb[mi] + kb2);
                LDSM_X4(aL[mi][0], aL[mi][1], aL[mi][2], aL[mi][3], aLb[mi] + kb2);
            }
            #pragma unroll
            for (int nip = 0; nip < 4; nip++) {
                LDSM_X4(bH[nip][0], bH[nip][1], bH[nip][2], bH[nip][3], bHb[nip] + kofs + kb2);
                LDSM_X4(bL[nip][0], bL[nip][1], bL[nip][2], bL[nip][3], bLb[nip] + kofs + kb2);
            }
            #pragma unroll
            for (int nip = 0; nip < 4; nip++)
                #pragma unroll
                for (int hh = 0; hh < 2; hh++) {
                    int ni = nip * 2 + hh;
                    unsigned b0 = bH[nip][hh * 2], b1 = bH[nip][hh * 2 + 1];
                    unsigned l0 = bL[nip][hh * 2], l1 = bL[nip][hh * 2 + 1];
                    #pragma unroll
                    for (int mi = 0; mi < 2; mi++) {
                        MMA_BF16(acc[mi][ni], aH[mi][0], aH[mi][1], aH[mi][2], aH[mi][3], b0, b1);
                        MMA_BF16(acc[mi][ni], aH[mi][0], aH[mi][1], aH[mi][2], aH[mi][3], l0, l1);
                        MMA_BF16(acc[mi][ni], aL[mi][0], aL[mi][1], aL[mi][2], aL[mi][3], b0, b1);
                    }
                }
        }

        // ---- exp -> gmem P + smem tile + rowsum ----
        #pragma unroll
        for (int mi = 0; mi < 2; mi++)
            #pragma unroll
            for (int ni = 0; ni < 8; ni++) {
                int rl = wm + mi * 16 + gr;
                int c  = wn + ni * 8 + gc * 2;
                float* cc = acc[mi][ni];
                float e0 = __expf(cc[0] * 0.125f);
                float e1 = __expf(cc[1] * 0.125f);
                float e2 = __expf(cc[2] * 0.125f);
                float e3 = __expf(cc[3] * 0.125f);
                __half2 h0 = __floats2half2_rn(e0, e1);
                __half2 h1 = __floats2half2_rn(e2, e3);
                __stcs((int*)&P[(size_t)(m0 + rl) * SEQX + n0 + c], *(int*)&h0);
                __stcs((int*)&P[(size_t)(m0 + rl + 8) * SEQX + n0 + c], *(int*)&h1);
                *(__half2*)&sPT[rl * SAP + c]       = h0;
                *(__half2*)&sPT[(rl + 8) * SAP + c] = h1;
                rowsum[mi * 2]     += e0 + e1;
                rowsum[mi * 2 + 1] += e2 + e3;
            }
        __syncthreads();

        // ---- AV: Oacc += Ptile @ Vtile^T ----
        #pragma unroll
        for (int ks = 0; ks < 8; ks++) {
            const int kb2 = ks * 32;
            unsigned a[2][4], vH[2][4], vL[2][4];
            #pragma unroll
            for (int mi = 0; mi < 2; mi++)
                LDSM_X4(a[mi][0], a[mi][1], a[mi][2], a[mi][3], pab[mi] + kb2);
            #pragma unroll
            for (int nip = 0; nip < 2; nip++) {
                LDSM_X4(vH[nip][0], vH[nip][1], vH[nip][2], vH[nip][3], vHb[nip] + vofs + kb2);
                LDSM_X4(vL[nip][0], vL[nip][1], vL[nip][2], vL[nip][3], vLb[nip] + vofs + kb2);
            }
            #pragma unroll
            for (int mi = 0; mi < 2; mi++)
                #pragma unroll
                for (int nip = 0; nip < 2; nip++)
                    #pragma unroll
                    for (int hh = 0; hh < 2; hh++) {
                        int ni = nip * 2 + hh;
                        MMA_F16(Oacc[mi][ni], a[mi][0], a[mi][1], a[mi][2], a[mi][3],
                                vH[nip][hh * 2], vH[nip][hh * 2 + 1]);
                        MMA_F16(Oacc[mi][ni], a[mi][0], a[mi][1], a[mi][2], a[mi][3],
                                vL[nip][hh * 2], vL[nip][hh * 2 + 1]);
                    }
        }
    }

    // ---- finalize rowsum ----
    #pragma unroll
    for (int j = 0; j < 4; j++) {
        rowsum[j] += __shfl_xor_sync(0xffffffffu, rowsum[j], 1);
        rowsum[j] += __shfl_xor_sync(0xffffffffu, rowsum[j], 2);
    }
    const int wnh = warp >> 2;
    if (gc == 0) {
        sPsum[wnh * 128 + wm + gr]      = rowsum[0];
        sPsum[wnh * 128 + wm + 8 + gr]  = rowsum[1];
        sPsum[wnh * 128 + wm + 16 + gr] = rowsum[2];
        sPsum[wnh * 128 + wm + 24 + gr] = rowsum[3];
    }
    __syncthreads();
    if (tid < 128) {
        float inv = 1.0f / (sPsum[tid] + sPsum[128 + tid]);
        sInv[tid] = inv;
        rinv[m0 + tid] = inv;
    }
    __syncthreads();

    // ---- scale + store O ----
    #pragma unroll
    for (int mi = 0; mi < 2; mi++)
        #pragma unroll
        for (int ni = 0; ni < 4; ni++) {
            int rl = wm + mi * 16 + gr;
            int c  = wd + ni * 8 + gc * 2;
            float inv0 = sInv[rl], inv1 = sInv[rl + 8];
            float* cc = Oacc[mi][ni];
            *(float2*)&O[(size_t)(m0 + rl) * D_MODELX + c] =
                make_float2(cc[0] * inv0, cc[1] * inv0);
            *(float2*)&O[(size_t)(m0 + rl + 8) * D_MODELX + c] =
                make_float2(cc[2] * inv1, cc[3] * inv1);
        }
}

// ============================================================================
// avg: barrier-free head average.
// ============================================================================
__global__ __launch_bounds__(256)
void avg_kernel(const __half* __restrict__ P, const float* __restrict__ rinv,
                float* __restrict__ avg)
{
    const int bq = blockIdx.x;
    const int t  = threadIdx.x;
    const int b  = bq >> 11;
    const int q  = bq & 2047;

    float acc[8] = {};

    #pragma unroll 4
    for (int h = 0; h < NUM_HEADSX; ++h) {
        const int z = b * 16 + h;
        float inv = rinv[(size_t)z * SEQX + q];
        const uint4* p4 = (const uint4*)(P + ((size_t)z * SEQX + q) * SEQX);
        uint4 u = __ldcs(p4 + t);
        float2 v0 = __half22float2(*reinterpret_cast<__half2*>(&u.x));
        float2 v1 = __half22float2(*reinterpret_cast<__half2*>(&u.y));
        float2 v2 = __half22float2(*reinterpret_cast<__half2*>(&u.z));
        float2 v3 = __half22float2(*reinterpret_cast<__half2*>(&u.w));
        acc[0] += v0.x * inv; acc[1] += v0.y * inv;
        acc[2] += v1.x * inv; acc[3] += v1.y * inv;
        acc[4] += v2.x * inv; acc[5] += v2.y * inv;
        acc[6] += v3.x * inv; acc[7] += v3.y * inv;
    }

    float* a = avg + (size_t)bq * SEQX + t * 8;
    float4 o0 = make_float4(acc[0] * (1.0f / NUM_HEADSX), acc[1] * (1.0f / NUM_HEADSX),
                            acc[2] * (1.0f / NUM_HEADSX), acc[3] * (1.0f / NUM_HEADSX));
    float4 o1 = make_float4(acc[4] * (1.0f / NUM_HEADSX), acc[5] * (1.0f / NUM_HEADSX),
                            acc[6] * (1.0f / NUM_HEADSX), acc[7] * (1.0f / NUM_HEADSX));
    __stcs((float4*)a, o0);
    __stcs((float4*)(a + 4), o1);
}

// ============================================================================
// launch
// ============================================================================
extern "C" void kernel_launch(void* const* d_in, const int* in_sizes, int n_in,
                              void* d_out, int out_size)
{
    const float* x_q = (const float*)d_in[0];
    const float* x_k = (const float*)d_in[1];
    const float* x_v = (const float*)d_in[2];
    const float* Wq  = (const float*)d_in[3];
    const float* bq  = (const float*)d_in[4];
    const float* Wk  = (const float*)d_in[5];
    const float* bk  = (const float*)d_in[6];
    const float* Wv  = (const float*)d_in[7];
    const float* bv  = (const float*)d_in[8];
    const float* Wo  = (const float*)d_in[9];
    const float* bo  = (const float*)d_in[10];

    float* out = (float*)d_out;
    float* avg = out + (size_t)M_TOK * D_MODELX;

    __nv_bfloat16 *Qh, *Ql, *Kh, *Kl;
    __half *Vth, *Vtl, *P;
    float *gO, *rinv;
    cudaGetSymbolAddress((void**)&Qh, g_Qh);
    cudaGetSymbolAddress((void**)&Ql, g_Ql);
    cudaGetSymbolAddress((void**)&Kh, g_Kh);
    cudaGetSymbolAddress((void**)&Kl, g_Kl);
    cudaGetSymbolAddress((void**)&Vth, g_Vth);
    cudaGetSymbolAddress((void**)&Vtl, g_Vtl);
    cudaGetSymbolAddress((void**)&gO, g_O);
    cudaGetSymbolAddress((void**)&P, g_P);
    cudaGetSymbolAddress((void**)&rinv, g_rinv);

    cudaFuncSetAttribute(fused_attn, cudaFuncAttributeMaxDynamicSharedMemorySize,
                         FUSED_SMEM);

    dim3 blk(256);
    dim3 gproj(D_MODELX / 64, M_TOK / 128, 1);   // (16, 64)

    // 1-3) projections (R12 kernels)
    mma_gemm<5><<<gproj, blk>>>(x_q, Wq, nullptr, Qh, Ql,
                                D_MODELX, D_MODELX, D_MODELX, D_MODELX, bq);
    mma_gemm<5><<<gproj, blk>>>(x_k, Wk, nullptr, Kh, Kl,
                                D_MODELX, D_MODELX, D_MODELX, D_MODELX, bk);
    mma_gemm<3><<<gproj, blk>>>(x_v, Wv, nullptr, Vth, Vtl,
                                D_MODELX, D_MODELX, 0, D_MODELX, bv);

    // 4) fused scores + softmax + AV (cp.async pipelined)
    dim3 gf(SEQX / 128, 1, NZ);                  // (16, 1, 64)
    fused_attn<<<gf, blk, FUSED_SMEM>>>(Qh, Ql, Kh, Kl, Vth, Vtl, P, rinv, gO);

    // 5) head-average
    avg_kernel<<<M_TOK, blk>>>(P, rinv, avg);

    // 6) output projection
    mma_gemm<0><<<gproj, blk>>>(gO, Wo, out, nullptr, nullptr,
                                D_MODELX, D_MODELX, D_MODELX, D_MODELX, bo);
}

// round 15
// speedup vs baseline: 1.1808x; 1.0592x over previous
#include <cuda_runtime.h>
#include <cuda_bf16.h>
#include <cuda_fp16.h>
#include <cstdint>

#define D_MODELX 1024
#define NUM_HEADSX 16
#define D_HEADX 64
#define BATCHX 4
#define SEQX 2048
#define M_TOK (BATCHX * SEQX)    // 8192
#define NZ (BATCHX * NUM_HEADSX) // 64

// ---- static device scratch ----
__device__ __nv_bfloat16 g_Qh[(size_t)M_TOK * D_MODELX];
__device__ __nv_bfloat16 g_Ql[(size_t)M_TOK * D_MODELX];
__device__ __nv_bfloat16 g_Kh[(size_t)M_TOK * D_MODELX];
__device__ __nv_bfloat16 g_Kl[(size_t)M_TOK * D_MODELX];
__device__ __half g_Vth[(size_t)M_TOK * D_MODELX];  // [Z][64][2048] fp16
__device__ float  g_O[(size_t)M_TOK * D_MODELX];
__device__ __half g_P[(size_t)NZ * SEQX * SEQX];    // 0.5 GiB fp16 exp(scores)
__device__ float  g_rinv[(size_t)NZ * SEQX];

__device__ __forceinline__ unsigned pack_bf2(float x, float y) {
    __nv_bfloat162 t = __floats2bfloat162_rn(x, y);
    return *reinterpret_cast<unsigned*>(&t);
}

__device__ __forceinline__ unsigned smem_u32(const void* p) {
    return (unsigned)__cvta_generic_to_shared(p);
}

#define LDSM_X4(r0, r1, r2, r3, addr)                                         \
    asm volatile("ldmatrix.sync.aligned.m8n8.x4.shared.b16 {%0,%1,%2,%3}, [%4];" \
        : "=r"(r0), "=r"(r1), "=r"(r2), "=r"(r3) : "r"(addr))

#define MMA_BF16(c, a0, a1, a2, a3, b0, b1)                                   \
    asm volatile(                                                             \
        "mma.sync.aligned.m16n8k16.row.col.f32.bf16.bf16.f32 "                \
        "{%0,%1,%2,%3},{%4,%5,%6,%7},{%8,%9},{%0,%1,%2,%3};"                  \
        : "+f"(c[0]), "+f"(c[1]), "+f"(c[2]), "+f"(c[3])                      \
        : "r"(a0), "r"(a1), "r"(a2), "r"(a3), "r"(b0), "r"(b1))

#define MMA_F16(c, a0, a1, a2, a3, b0, b1)                                    \
    asm volatile(                                                             \
        "mma.sync.aligned.m16n8k16.row.col.f32.f16.f16.f32 "                  \
        "{%0,%1,%2,%3},{%4,%5,%6,%7},{%8,%9},{%0,%1,%2,%3};"                  \
        : "+f"(c[0]), "+f"(c[1]), "+f"(c[2]), "+f"(c[3])                      \
        : "r"(a0), "r"(a1), "r"(a2), "r"(a3), "r"(b0), "r"(b1))

#define CP_ASYNC16(dst, src)                                                  \
    asm volatile("cp.async.cg.shared.global [%0], [%1], 16;"                  \
        :: "r"(dst), "l"(src) : "memory")
#define CP_COMMIT() asm volatile("cp.async.commit_group;" ::: "memory")
#define CP_WAIT_ALL() asm volatile("cp.async.wait_group 0;" ::: "memory")

// ============================================================================
// NT bf16-split MMA GEMM (fp32 in, split in-kernel): C = A @ B^T + bias
// MODE 0: fp32 out + bias; MODE 3: V proj transposed fp16 (hi only);
// MODE 5: Q/K proj bf16 hi/lo + bias.  128x64x32, 256 threads.
// ============================================================================
template <int MODE>
__global__ __launch_bounds__(256)
void mma_gemm(const float* __restrict__ A,
              const float* __restrict__ B,
              float* __restrict__ C,
              void* __restrict__ Chv, void* __restrict__ Clv,
              int lda, int ldb, int ldc,
              int K, const float* __restrict__ bias)
{
    constexpr int BM = 128, BN = 64, BK = 32;
    constexpr int SA = 40;

    __shared__ __align__(16) __nv_bfloat16 AsH[BM * SA];
    __shared__ __align__(16) __nv_bfloat16 AsL[BM * SA];
    __shared__ __align__(16) __nv_bfloat16 BsH[BN * SA];
    __shared__ __align__(16) __nv_bfloat16 BsL[BN * SA];

    const int tid  = threadIdx.x;
    const int m0   = blockIdx.y * BM;
    const int n0   = blockIdx.x * BN;
    const int warp = tid >> 5, lane = tid & 31;
    const int wm = (warp & 3) * 32;
    const int wn = (warp >> 2) * 32;
    const int gr = lane >> 2;
    const int gc = lane & 3;
    const int ti = lane >> 3, ri = lane & 7;

    unsigned aHb[2], aLb[2], bHb[2], bLb[2];
    #pragma unroll
    for (int mi = 0; mi < 2; mi++) {
        int row = wm + mi * 16 + (ti & 1) * 8 + ri;
        int col = (ti >> 1) * 8;
        aHb[mi] = smem_u32(&AsH[row * SA + col]);
        aLb[mi] = smem_u32(&AsL[row * SA + col]);
    }
    #pragma unroll
    for (int nip = 0; nip < 2; nip++) {
        int row = wn + (nip * 2 + (ti >> 1)) * 8 + ri;
        int col = (ti & 1) * 8;
        bHb[nip] = smem_u32(&BsH[row * SA + col]);
        bLb[nip] = smem_u32(&BsL[row * SA + col]);
    }

    float acc[2][4][4] = {};
    float4 ra[4], rb[2];

    {
        #pragma unroll
        for (int i = 0; i < 4; i++) {
            int idx = tid + i * 256, row = idx >> 3, c4 = idx & 7;
            ra[i] = *(const float4*)(A + (size_t)(m0 + row) * lda + c4 * 4);
        }
        #pragma unroll
        for (int i = 0; i < 2; i++) {
            int idx = tid + i * 256, row = idx >> 3, c4 = idx & 7;
            rb[i] = *(const float4*)(B + (size_t)(n0 + row) * ldb + c4 * 4);
        }
    }

    const int niter = K / BK;
    for (int it = 0; it < niter; ++it) {
        #pragma unroll
        for (int i = 0; i < 4; i++) {
            int idx = tid + i * 256, row = idx >> 3, c4 = idx & 7;
            float v0 = ra[i].x, v1 = ra[i].y, v2 = ra[i].z, v3 = ra[i].w;
            float h0 = __bfloat162float(__float2bfloat16_rn(v0));
            float h1 = __bfloat162float(__float2bfloat16_rn(v1));
            float h2 = __bfloat162float(__float2bfloat16_rn(v2));
            float h3 = __bfloat162float(__float2bfloat16_rn(v3));
            uint2 H, L;
            H.x = pack_bf2(v0, v1); H.y = pack_bf2(v2, v3);
            L.x = pack_bf2(v0 - h0, v1 - h1); L.y = pack_bf2(v2 - h2, v3 - h3);
            *(uint2*)&AsH[row * SA + c4 * 4] = H;
            *(uint2*)&AsL[row * SA + c4 * 4] = L;
        }
        #pragma unroll
        for (int i = 0; i < 2; i++) {
            int idx = tid + i * 256, row = idx >> 3, c4 = idx & 7;
            float v0 = rb[i].x, v1 = rb[i].y, v2 = rb[i].z, v3 = rb[i].w;
            float h0 = __bfloat162float(__float2bfloat16_rn(v0));
            float h1 = __bfloat162float(__float2bfloat16_rn(v1));
            float h2 = __bfloat162float(__float2bfloat16_rn(v2));
            float h3 = __bfloat162float(__float2bfloat16_rn(v3));
            uint2 H, L;
            H.x = pack_bf2(v0, v1); H.y = pack_bf2(v2, v3);
            L.x = pack_bf2(v0 - h0, v1 - h1); L.y = pack_bf2(v2 - h2, v3 - h3);
            *(uint2*)&BsH[row * SA + c4 * 4] = H;
            *(uint2*)&BsL[row * SA + c4 * 4] = L;
        }
        __syncthreads();

        if (it + 1 < niter) {
            int k0 = (it + 1) * BK;
            #pragma unroll
            for (int i = 0; i < 4; i++) {
                int idx = tid + i * 256, row = idx >> 3, c4 = idx & 7;
                ra[i] = *(const float4*)(A + (size_t)(m0 + row) * lda + k0 + c4 * 4);
            }
            #pragma unroll
            for (int i = 0; i < 2; i++) {
                int idx = tid + i * 256, row = idx >> 3, c4 = idx & 7;
                rb[i] = *(const float4*)(B + (size_t)(n0 + row) * ldb + k0 + c4 * 4);
            }
        }

        #pragma unroll
        for (int ks = 0; ks < 2; ks++) {
            const int kb2 = ks * 32;
            unsigned aH[2][4], aL[2][4], bH[2][4], bL[2][4];
            #pragma unroll
            for (int mi = 0; mi < 2; mi++) {
                LDSM_X4(aH[mi][0], aH[mi][1], aH[mi][2], aH[mi][3], aHb[mi] + kb2);
                LDSM_X4(aL[mi][0], aL[mi][1], aL[mi][2], aL[mi][3], aLb[mi] + kb2);
            }
            #pragma unroll
            for (int nip = 0; nip < 2; nip++) {
                LDSM_X4(bH[nip][0], bH[nip][1], bH[nip][2], bH[nip][3], bHb[nip] + kb2);
                LDSM_X4(bL[nip][0], bL[nip][1], bL[nip][2], bL[nip][3], bLb[nip] + kb2);
            }
            #pragma unroll
            for (int mi = 0; mi < 2; mi++)
                #pragma unroll
                for (int nip = 0; nip < 2; nip++)
                    #pragma unroll
                    for (int hh = 0; hh < 2; hh++) {
                        int ni = nip * 2 + hh;
                        unsigned b0 = bH[nip][hh * 2], b1 = bH[nip][hh * 2 + 1];
                        unsigned l0 = bL[nip][hh * 2], l1 = bL[nip][hh * 2 + 1];
                        MMA_BF16(acc[mi][ni], aH[mi][0], aH[mi][1], aH[mi][2], aH[mi][3], b0, b1);
                        MMA_BF16(acc[mi][ni], aH[mi][0], aH[mi][1], aH[mi][2], aH[mi][3], l0, l1);
                        MMA_BF16(acc[mi][ni], aL[mi][0], aL[mi][1], aL[mi][2], aL[mi][3], b0, b1);
                    }
        }
        __syncthreads();
    }

    #pragma unroll
    for (int mi = 0; mi < 2; mi++)
        #pragma unroll
        for (int ni = 0; ni < 4; ni++) {
            int r = m0 + wm + mi * 16 + gr;
            int c = n0 + wn + ni * 8 + gc * 2;
            float* cc = acc[mi][ni];
            if (MODE == 3) {
                __half* Ch = (__half*)Chv;
                int b = r >> 11, s = r & 2047;
                int h = c >> 6, d = c & 63;
                float b0 = bias[c], b1 = bias[c + 1];
                size_t base = ((size_t)(b * 16 + h) * 64 + d) * 2048;
                Ch[base + s]            = __float2half_rn(cc[0] + b0);
                Ch[base + 2048 + s]     = __float2half_rn(cc[1] + b1);
                Ch[base + s + 8]        = __float2half_rn(cc[2] + b0);
                Ch[base + 2048 + s + 8] = __float2half_rn(cc[3] + b1);
            } else if (MODE == 5) {
                __nv_bfloat16* Ch = (__nv_bfloat16*)Chv;
                __nv_bfloat16* Cl = (__nv_bfloat16*)Clv;
                float b0 = bias[c], b1 = bias[c + 1];
                float v00 = cc[0] + b0, v01 = cc[1] + b1;
                float v10 = cc[2] + b0, v11 = cc[3] + b1;
                float h00 = __bfloat162float(__float2bfloat16_rn(v00));
                float h01 = __bfloat162float(__float2bfloat16_rn(v01));
                float h10 = __bfloat162float(__float2bfloat16_rn(v10));
                float h11 = __bfloat162float(__float2bfloat16_rn(v11));
                size_t o0 = (size_t)r * ldc + c;
                size_t o1 = (size_t)(r + 8) * ldc + c;
                *(unsigned*)&Ch[o0] = pack_bf2(v00, v01);
                *(unsigned*)&Ch[o1] = pack_bf2(v10, v11);
                *(unsigned*)&Cl[o0] = pack_bf2(v00 - h00, v01 - h01);
                *(unsigned*)&Cl[o1] = pack_bf2(v10 - h10, v11 - h11);
            } else {
                float b0 = 0.f, b1 = 0.f;
                if (bias) { b0 = bias[c]; b1 = bias[c + 1]; }
                float2 v0 = make_float2(cc[0] + b0, cc[1] + b1);
                float2 v1 = make_float2(cc[2] + b0, cc[3] + b1);
                *(float2*)&C[(size_t)r * ldc + c]       = v0;
                *(float2*)&C[(size_t)(r + 8) * ldc + c] = v1;
            }
        }
}

// ============================================================================
// Fused scores + softmax + AV, cp.async double-buffered K/V, V fp16 single-pass.
// One block per (z, 128-row m-tile), 256 threads. smem ~182 KB.
// ============================================================================
#define OQH   0
#define OQL   18432
#define OKH0  36864
#define OKH1  55296
#define OKL0  73728
#define OKL1  92160
#define OVH0  110592
#define OVH1  128000
#define OPT   145408
#define OINV  180224
#define OPSUM 180736
#define FUSED_SMEM 181760
#define KBUF_STRIDE 18432
#define VBUF_STRIDE 17408
#define SAQ 72
#define SAP 136

__global__ void __launch_bounds__(256, 1)
fused_attn(const __nv_bfloat16* __restrict__ Qh, const __nv_bfloat16* __restrict__ Ql,
           const __nv_bfloat16* __restrict__ Kh, const __nv_bfloat16* __restrict__ Kl,
           const __half* __restrict__ Vh,
           __half* __restrict__ P, float* __restrict__ rinv,
           float* __restrict__ O)
{
    extern __shared__ char sm[];
    __nv_bfloat16* sQH = (__nv_bfloat16*)(sm + OQH);
    __nv_bfloat16* sQL = (__nv_bfloat16*)(sm + OQL);
    __half* sPT = (__half*)(sm + OPT);
    float* sInv  = (float*)(sm + OINV);
    float* sPsum = (float*)(sm + OPSUM);

    const unsigned kh0 = smem_u32(sm + OKH0);
    const unsigned kl0 = smem_u32(sm + OKL0);
    const unsigned vh0 = smem_u32(sm + OVH0);

    const int z = blockIdx.z, bb = z >> 4, hh_ = z & 15;
    const int m0 = blockIdx.x * 128;
    const size_t qoff = (size_t)bb * SEQX * D_MODELX + (size_t)hh_ * D_HEADX;
    Qh += qoff; Ql += qoff; Kh += qoff; Kl += qoff;
    Vh += (size_t)z * D_HEADX * SEQX;
    P  += (size_t)z * SEQX * SEQX;
    rinv += (size_t)z * SEQX;
    O  += qoff;

    const int tid  = threadIdx.x;
    const int warp = tid >> 5, lane = tid & 31;
    const int wm = (warp & 3) * 32;
    const int wn = (warp >> 2) * 64;
    const int wd = (warp >> 2) * 32;
    const int gr = lane >> 2;
    const int gc = lane & 3;
    const int ti = lane >> 3, ri = lane & 7;

    // ---- load Q tile once ----
    #pragma unroll
    for (int i = 0; i < 4; i++) {
        int idx = tid + i * 256, row = idx >> 3, c8 = idx & 7;
        size_t oa = (size_t)(m0 + row) * D_MODELX + c8 * 8;
        *(uint4*)&sQH[row * SAQ + c8 * 8] = *(const uint4*)(Qh + oa);
        *(uint4*)&sQL[row * SAQ + c8 * 8] = *(const uint4*)(Ql + oa);
    }

    // ---- prefetch K/V tile 0 ----
    {
        #pragma unroll
        for (int i = 0; i < 4; i++) {
            int idx = tid + i * 256, row = idx >> 3, c8 = idx & 7;
            unsigned so = (unsigned)(row * SAQ + c8 * 8) * 2;
            CP_ASYNC16(kh0 + so, Kh + (size_t)row * D_MODELX + c8 * 8);
            CP_ASYNC16(kl0 + so, Kl + (size_t)row * D_MODELX + c8 * 8);
        }
        #pragma unroll
        for (int i = 0; i < 4; i++) {
            int idx = tid + i * 256, row = idx >> 4, c16 = idx & 15;
            unsigned so = (unsigned)(row * SAP + c16 * 8) * 2;
            CP_ASYNC16(vh0 + so, Vh + (size_t)row * SEQX + c16 * 8);
        }
        CP_COMMIT();
    }

    unsigned aHb[2], aLb[2], bHb[4], bLb[4], pab[2], vHb[2];
    #pragma unroll
    for (int mi = 0; mi < 2; mi++) {
        int row = wm + mi * 16 + (ti & 1) * 8 + ri;
        int col = (ti >> 1) * 8;
        aHb[mi] = smem_u32(&sQH[row * SAQ + col]);
        aLb[mi] = smem_u32(&sQL[row * SAQ + col]);
        pab[mi] = smem_u32(&sPT[row * SAP + col]);
    }
    #pragma unroll
    for (int nip = 0; nip < 4; nip++) {
        int row = wn + (nip * 2 + (ti >> 1)) * 8 + ri;
        int col = (ti & 1) * 8;
        bHb[nip] = kh0 + (unsigned)(row * SAQ + col) * 2;
        bLb[nip] = kl0 + (unsigned)(row * SAQ + col) * 2;
    }
    #pragma unroll
    for (int nip = 0; nip < 2; nip++) {
        int row = wd + (nip * 2 + (ti >> 1)) * 8 + ri;
        int col = (ti & 1) * 8;
        vHb[nip] = vh0 + (unsigned)(row * SAP + col) * 2;
    }

    float Oacc[2][4][4] = {};
    float rowsum[4] = {0.f, 0.f, 0.f, 0.f};

    for (int nb = 0; nb < 16; nb++) {
        const int n0 = nb * 128;
        const unsigned kofs = (unsigned)(nb & 1) * KBUF_STRIDE;
        const unsigned vofs = (unsigned)(nb & 1) * VBUF_STRIDE;

        CP_WAIT_ALL();
        __syncthreads();

        if (nb + 1 < 16) {
            const int n1 = n0 + 128;
            const unsigned kn = (unsigned)((nb + 1) & 1) * KBUF_STRIDE;
            const unsigned vn = (unsigned)((nb + 1) & 1) * VBUF_STRIDE;
            #pragma unroll
            for (int i = 0; i < 4; i++) {
                int idx = tid + i * 256, row = idx >> 3, c8 = idx & 7;
                unsigned so = (unsigned)(row * SAQ + c8 * 8) * 2;
                CP_ASYNC16(kh0 + kn + so, Kh + (size_t)(n1 + row) * D_MODELX + c8 * 8);
                CP_ASYNC16(kl0 + kn + so, Kl + (size_t)(n1 + row) * D_MODELX + c8 * 8);
            }
            #pragma unroll
            for (int i = 0; i < 4; i++) {
                int idx = tid + i * 256, row = idx >> 4, c16 = idx & 15;
                unsigned so = (unsigned)(row * SAP + c16 * 8) * 2;
                CP_ASYNC16(vh0 + vn + so, Vh + (size_t)row * SEQX + n1 + c16 * 8);
            }
            CP_COMMIT();
        }

        // ---- scores: S = QK^T, 3-pass bf16 ----
        float acc[2][8][4] = {};
        #pragma unroll
        for (int ks = 0; ks < 4; ks++) {
            const int kb2 = ks * 32;
            unsigned aH[2][4], aL[2][4], bH[4][4], bL[4][4];
            #pragma unroll
            for (int mi = 0; mi < 2; mi++) {
                LDSM_X4(aH[mi][0], aH[mi][1], aH[mi][2], aH[mi][3], aHb[mi] + kb2);
                LDSM_X4(aL[mi][0], aL[mi][1], aL[mi][2], aL[mi][3], aLb[mi] + kb2);
            }
            #pragma unroll
            for (int nip = 0; nip < 4; nip++) {
                LDSM_X4(bH[nip][0], bH[nip][1], bH[nip][2], bH[nip][3], bHb[nip] + kofs + kb2);
                LDSM_X4(bL[nip][0], bL[nip][1], bL[nip][2], bL[nip][3], bLb[nip] + kofs + kb2);
            }
            #pragma unroll
            for (int nip = 0; nip < 4; nip++)
                #pragma unroll
                for (int hh = 0; hh < 2; hh++) {
                    int ni = nip * 2 + hh;
                    unsigned b0 = bH[nip][hh * 2], b1 = bH[nip][hh * 2 + 1];
                    unsigned l0 = bL[nip][hh * 2], l1 = bL[nip][hh * 2 + 1];
                    #pragma unroll
                    for (int mi = 0; mi < 2; mi++) {
                        MMA_BF16(acc[mi][ni], aH[mi][0], aH[mi][1], aH[mi][2], aH[mi][3], b0, b1);
                        MMA_BF16(acc[mi][ni], aH[mi][0], aH[mi][1], aH[mi][2], aH[mi][3], l0, l1);
                        MMA_BF16(acc[mi][ni], aL[mi][0], aL[mi][1], aL[mi][2], aL[mi][3], b0, b1);
                    }
                }
        }

        // ---- exp -> gmem P + smem tile + rowsum ----
        #pragma unroll
        for (int mi = 0; mi < 2; mi++)
            #pragma unroll
            for (int ni = 0; ni < 8; ni++) {
                int rl = wm + mi * 16 + gr;
                int c  = wn + ni * 8 + gc * 2;
                float* cc = acc[mi][ni];
                float e0 = __expf(cc[0] * 0.125f);
                float e1 = __expf(cc[1] * 0.125f);
                float e2 = __expf(cc[2] * 0.125f);
                float e3 = __expf(cc[3] * 0.125f);
                __half2 h0 = __floats2half2_rn(e0, e1);
                __half2 h1 = __floats2half2_rn(e2, e3);
                __stcs((int*)&P[(size_t)(m0 + rl) * SEQX + n0 + c], *(int*)&h0);
                __stcs((int*)&P[(size_t)(m0 + rl + 8) * SEQX + n0 + c], *(int*)&h1);
                *(__half2*)&sPT[rl * SAP + c]       = h0;
                *(__half2*)&sPT[(rl + 8) * SAP + c] = h1;
                rowsum[mi * 2]     += e0 + e1;
                rowsum[mi * 2 + 1] += e2 + e3;
            }
        __syncthreads();

        // ---- AV: Oacc += Ptile @ Vtile^T (V fp16 single-pass) ----
        #pragma unroll
        for (int ks = 0; ks < 8; ks++) {
            const int kb2 = ks * 32;
            unsigned a[2][4], vH[2][4];
            #pragma unroll
            for (int mi = 0; mi < 2; mi++)
                LDSM_X4(a[mi][0], a[mi][1], a[mi][2], a[mi][3], pab[mi] + kb2);
            #pragma unroll
            for (int nip = 0; nip < 2; nip++)
                LDSM_X4(vH[nip][0], vH[nip][1], vH[nip][2], vH[nip][3], vHb[nip] + vofs + kb2);
            #pragma unroll
            for (int mi = 0; mi < 2; mi++)
                #pragma unroll
                for (int nip = 0; nip < 2; nip++)
                    #pragma unroll
                    for (int hh = 0; hh < 2; hh++) {
                        int ni = nip * 2 + hh;
                        MMA_F16(Oacc[mi][ni], a[mi][0], a[mi][1], a[mi][2], a[mi][3],
                                vH[nip][hh * 2], vH[nip][hh * 2 + 1]);
                    }
        }
    }

    // ---- finalize rowsum ----
    #pragma unroll
    for (int j = 0; j < 4; j++) {
        rowsum[j] += __shfl_xor_sync(0xffffffffu, rowsum[j], 1);
        rowsum[j] += __shfl_xor_sync(0xffffffffu, rowsum[j], 2);
    }
    const int wnh = warp >> 2;
    if (gc == 0) {
        sPsum[wnh * 128 + wm + gr]      = rowsum[0];
        sPsum[wnh * 128 + wm + 8 + gr]  = rowsum[1];
        sPsum[wnh * 128 + wm + 16 + gr] = rowsum[2];
        sPsum[wnh * 128 + wm + 24 + gr] = rowsum[3];
    }
    __syncthreads();
    if (tid < 128) {
        float inv = 1.0f / (sPsum[tid] + sPsum[128 + tid]);
        sInv[tid] = inv;
        rinv[m0 + tid] = inv;
    }
    __syncthreads();

    // ---- scale + store O ----
    #pragma unroll
    for (int mi = 0; mi < 2; mi++)
        #pragma unroll
        for (int ni = 0; ni < 4; ni++) {
            int rl = wm + mi * 16 + gr;
            int c  = wd + ni * 8 + gc * 2;
            float inv0 = sInv[rl], inv1 = sInv[rl + 8];
            float* cc = Oacc[mi][ni];
            *(float2*)&O[(size_t)(m0 + rl) * D_MODELX + c] =
                make_float2(cc[0] * inv0, cc[1] * inv0);
            *(float2*)&O[(size_t)(m0 + rl + 8) * D_MODELX + c] =
                make_float2(cc[2] * inv1, cc[3] * inv1);
        }
}

// ============================================================================
// avg: barrier-free head average, deeper unroll for MLP.
// ============================================================================
__global__ __launch_bounds__(256)
void avg_kernel(const __half* __restrict__ P, const float* __restrict__ rinv,
                float* __restrict__ avg)
{
    const int bq = blockIdx.x;
    const int t  = threadIdx.x;
    const int b  = bq >> 11;
    const int q  = bq & 2047;

    float acc[8] = {};

    #pragma unroll 8
    for (int h = 0; h < NUM_HEADSX; ++h) {
        const int z = b * 16 + h;
        float inv = rinv[(size_t)z * SEQX + q];
        const uint4* p4 = (const uint4*)(P + ((size_t)z * SEQX + q) * SEQX);
        uint4 u = __ldcs(p4 + t);
        float2 v0 = __half22float2(*reinterpret_cast<__half2*>(&u.x));
        float2 v1 = __half22float2(*reinterpret_cast<__half2*>(&u.y));
        float2 v2 = __half22float2(*reinterpret_cast<__half2*>(&u.z));
        float2 v3 = __half22float2(*reinterpret_cast<__half2*>(&u.w));
        acc[0] += v0.x * inv; acc[1] += v0.y * inv;
        acc[2] += v1.x * inv; acc[3] += v1.y * inv;
        acc[4] += v2.x * inv; acc[5] += v2.y * inv;
        acc[6] += v3.x * inv; acc[7] += v3.y * inv;
    }

    float* a = avg + (size_t)bq * SEQX + t * 8;
    float4 o0 = make_float4(acc[0] * (1.0f / NUM_HEADSX), acc[1] * (1.0f / NUM_HEADSX),
                            acc[2] * (1.0f / NUM_HEADSX), acc[3] * (1.0f / NUM_HEADSX));
    float4 o1 = make_float4(acc[4] * (1.0f / NUM_HEADSX), acc[5] * (1.0f / NUM_HEADSX),
                            acc[6] * (1.0f / NUM_HEADSX), acc[7] * (1.0f / NUM_HEADSX));
    __stcs((float4*)a, o0);
    __stcs((float4*)(a + 4), o1);
}

// ============================================================================
// launch
// ============================================================================
extern "C" void kernel_launch(void* const* d_in, const int* in_sizes, int n_in,
                              void* d_out, int out_size)
{
    const float* x_q = (const float*)d_in[0];
    const float* x_k = (const float*)d_in[1];
    const float* x_v = (const float*)d_in[2];
    const float* Wq  = (const float*)d_in[3];
    const float* bq  = (const float*)d_in[4];
    const float* Wk  = (const float*)d_in[5];
    const float* bk  = (const float*)d_in[6];
    const float* Wv  = (const float*)d_in[7];
    const float* bv  = (const float*)d_in[8];
    const float* Wo  = (const float*)d_in[9];
    const float* bo  = (const float*)d_in[10];

    float* out = (float*)d_out;
    float* avg = out + (size_t)M_TOK * D_MODELX;

    __nv_bfloat16 *Qh, *Ql, *Kh, *Kl;
    __half *Vth, *P;
    float *gO, *rinv;
    cudaGetSymbolAddress((void**)&Qh, g_Qh);
    cudaGetSymbolAddress((void**)&Ql, g_Ql);
    cudaGetSymbolAddress((void**)&Kh, g_Kh);
    cudaGetSymbolAddress((void**)&Kl, g_Kl);
    cudaGetSymbolAddress((void**)&Vth, g_Vth);
    cudaGetSymbolAddress((void**)&gO, g_O);
    cudaGetSymbolAddress((void**)&P, g_P);
    cudaGetSymbolAddress((void**)&rinv, g_rinv);

    cudaFuncSetAttribute(fused_attn, cudaFuncAttributeMaxDynamicSharedMemorySize,
                         FUSED_SMEM);

    dim3 blk(256);
    dim3 gproj(D_MODELX / 64, M_TOK / 128, 1);   // (16, 64)

    // 1-3) projections
    mma_gemm<5><<<gproj, blk>>>(x_q, Wq, nullptr, Qh, Ql,
                                D_MODELX, D_MODELX, D_MODELX, D_MODELX, bq);
    mma_gemm<5><<<gproj, blk>>>(x_k, Wk, nullptr, Kh, Kl,
                                D_MODELX, D_MODELX, D_MODELX, D_MODELX, bk);
    mma_gemm<3><<<gproj, blk>>>(x_v, Wv, nullptr, Vth, nullptr,
                                D_MODELX, D_MODELX, 0, D_MODELX, bv);

    // 4) fused scores + softmax + AV
    dim3 gf(SEQX / 128, 1, NZ);                  // (16, 1, 64)
    fused_attn<<<gf, blk, FUSED_SMEM>>>(Qh, Ql, Kh, Kl, Vth, P, rinv, gO);

    // 5) head-average
    avg_kernel<<<M_TOK, blk>>>(P, rinv, avg);

    // 6) output projection
    mma_gemm<0><<<gproj, blk>>>(gO, Wo, out, nullptr, nullptr,
                                D_MODELX, D_MODELX, D_MODELX, D_MODELX, bo);
}

// round 16
// speedup vs baseline: 1.2044x; 1.0199x over previous
#include <cuda_runtime.h>
#include <cuda_bf16.h>
#include <cuda_fp16.h>
#include <cstdint>

#define D_MODELX 1024
#define NUM_HEADSX 16
#define D_HEADX 64
#define BATCHX 4
#define SEQX 2048
#define M_TOK (BATCHX * SEQX)    // 8192
#define NZ (BATCHX * NUM_HEADSX) // 64

// ---- static device scratch ----
__device__ __nv_bfloat16 g_Qh[(size_t)M_TOK * D_MODELX];
__device__ __nv_bfloat16 g_Ql[(size_t)M_TOK * D_MODELX];
__device__ __nv_bfloat16 g_Kh[(size_t)M_TOK * D_MODELX];
__device__ __nv_bfloat16 g_Kl[(size_t)M_TOK * D_MODELX];
__device__ __half g_Vth[(size_t)M_TOK * D_MODELX];  // [Z][64][2048] fp16
__device__ float  g_O[(size_t)M_TOK * D_MODELX];
__device__ __half g_P[(size_t)NZ * SEQX * SEQX];    // 0.5 GiB fp16 exp(scores)
__device__ float  g_rinv[(size_t)NZ * SEQX];

__device__ __forceinline__ unsigned pack_bf2(float x, float y) {
    __nv_bfloat162 t = __floats2bfloat162_rn(x, y);
    return *reinterpret_cast<unsigned*>(&t);
}

__device__ __forceinline__ unsigned smem_u32(const void* p) {
    return (unsigned)__cvta_generic_to_shared(p);
}

#define LDSM_X4(r0, r1, r2, r3, addr)                                         \
    asm volatile("ldmatrix.sync.aligned.m8n8.x4.shared.b16 {%0,%1,%2,%3}, [%4];" \
        : "=r"(r0), "=r"(r1), "=r"(r2), "=r"(r3) : "r"(addr))

#define MMA_BF16(c, a0, a1, a2, a3, b0, b1)                                   \
    asm volatile(                                                             \
        "mma.sync.aligned.m16n8k16.row.col.f32.bf16.bf16.f32 "                \
        "{%0,%1,%2,%3},{%4,%5,%6,%7},{%8,%9},{%0,%1,%2,%3};"                  \
        : "+f"(c[0]), "+f"(c[1]), "+f"(c[2]), "+f"(c[3])                      \
        : "r"(a0), "r"(a1), "r"(a2), "r"(a3), "r"(b0), "r"(b1))

#define MMA_F16(c, a0, a1, a2, a3, b0, b1)                                    \
    asm volatile(                                                             \
        "mma.sync.aligned.m16n8k16.row.col.f32.f16.f16.f32 "                  \
        "{%0,%1,%2,%3},{%4,%5,%6,%7},{%8,%9},{%0,%1,%2,%3};"                  \
        : "+f"(c[0]), "+f"(c[1]), "+f"(c[2]), "+f"(c[3])                      \
        : "r"(a0), "r"(a1), "r"(a2), "r"(a3), "r"(b0), "r"(b1))

#define CP_ASYNC16(dst, src)                                                  \
    asm volatile("cp.async.cg.shared.global [%0], [%1], 16;"                  \
        :: "r"(dst), "l"(src) : "memory")
#define CP_COMMIT() asm volatile("cp.async.commit_group;" ::: "memory")
#define CP_WAIT_ALL() asm volatile("cp.async.wait_group 0;" ::: "memory")

// ============================================================================
// NT bf16-split MMA GEMM (fp32 in, split in-kernel): C = A @ B^T + bias
// MODE 0: fp32 out + bias; MODE 3: V proj transposed fp16 (hi only);
// MODE 5: Q/K proj bf16 hi/lo + bias.  128x64x32, 256 threads.
// ============================================================================
template <int MODE>
__global__ __launch_bounds__(256)
void mma_gemm(const float* __restrict__ A,
              const float* __restrict__ B,
              float* __restrict__ C,
              void* __restrict__ Chv, void* __restrict__ Clv,
              int lda, int ldb, int ldc,
              int K, const float* __restrict__ bias)
{
    constexpr int BM = 128, BN = 64, BK = 32;
    constexpr int SA = 40;

    __shared__ __align__(16) __nv_bfloat16 AsH[BM * SA];
    __shared__ __align__(16) __nv_bfloat16 AsL[BM * SA];
    __shared__ __align__(16) __nv_bfloat16 BsH[BN * SA];
    __shared__ __align__(16) __nv_bfloat16 BsL[BN * SA];

    const int tid  = threadIdx.x;
    const int m0   = blockIdx.y * BM;
    const int n0   = blockIdx.x * BN;
    const int warp = tid >> 5, lane = tid & 31;
    const int wm = (warp & 3) * 32;
    const int wn = (warp >> 2) * 32;
    const int gr = lane >> 2;
    const int gc = lane & 3;
    const int ti = lane >> 3, ri = lane & 7;

    unsigned aHb[2], aLb[2], bHb[2], bLb[2];
    #pragma unroll
    for (int mi = 0; mi < 2; mi++) {
        int row = wm + mi * 16 + (ti & 1) * 8 + ri;
        int col = (ti >> 1) * 8;
        aHb[mi] = smem_u32(&AsH[row * SA + col]);
        aLb[mi] = smem_u32(&AsL[row * SA + col]);
    }
    #pragma unroll
    for (int nip = 0; nip < 2; nip++) {
        int row = wn + (nip * 2 + (ti >> 1)) * 8 + ri;
        int col = (ti & 1) * 8;
        bHb[nip] = smem_u32(&BsH[row * SA + col]);
        bLb[nip] = smem_u32(&BsL[row * SA + col]);
    }

    float acc[2][4][4] = {};
    float4 ra[4], rb[2];

    {
        #pragma unroll
        for (int i = 0; i < 4; i++) {
            int idx = tid + i * 256, row = idx >> 3, c4 = idx & 7;
            ra[i] = *(const float4*)(A + (size_t)(m0 + row) * lda + c4 * 4);
        }
        #pragma unroll
        for (int i = 0; i < 2; i++) {
            int idx = tid + i * 256, row = idx >> 3, c4 = idx & 7;
            rb[i] = *(const float4*)(B + (size_t)(n0 + row) * ldb + c4 * 4);
        }
    }

    const int niter = K / BK;
    for (int it = 0; it < niter; ++it) {
        #pragma unroll
        for (int i = 0; i < 4; i++) {
            int idx = tid + i * 256, row = idx >> 3, c4 = idx & 7;
            float v0 = ra[i].x, v1 = ra[i].y, v2 = ra[i].z, v3 = ra[i].w;
            float h0 = __bfloat162float(__float2bfloat16_rn(v0));
            float h1 = __bfloat162float(__float2bfloat16_rn(v1));
            float h2 = __bfloat162float(__float2bfloat16_rn(v2));
            float h3 = __bfloat162float(__float2bfloat16_rn(v3));
            uint2 H, L;
            H.x = pack_bf2(v0, v1); H.y = pack_bf2(v2, v3);
            L.x = pack_bf2(v0 - h0, v1 - h1); L.y = pack_bf2(v2 - h2, v3 - h3);
            *(uint2*)&AsH[row * SA + c4 * 4] = H;
            *(uint2*)&AsL[row * SA + c4 * 4] = L;
        }
        #pragma unroll
        for (int i = 0; i < 2; i++) {
            int idx = tid + i * 256, row = idx >> 3, c4 = idx & 7;
            float v0 = rb[i].x, v1 = rb[i].y, v2 = rb[i].z, v3 = rb[i].w;
            float h0 = __bfloat162float(__float2bfloat16_rn(v0));
            float h1 = __bfloat162float(__float2bfloat16_rn(v1));
            float h2 = __bfloat162float(__float2bfloat16_rn(v2));
            float h3 = __bfloat162float(__float2bfloat16_rn(v3));
            uint2 H, L;
            H.x = pack_bf2(v0, v1); H.y = pack_bf2(v2, v3);
            L.x = pack_bf2(v0 - h0, v1 - h1); L.y = pack_bf2(v2 - h2, v3 - h3);
            *(uint2*)&BsH[row * SA + c4 * 4] = H;
            *(uint2*)&BsL[row * SA + c4 * 4] = L;
        }
        __syncthreads();

        if (it + 1 < niter) {
            int k0 = (it + 1) * BK;
            #pragma unroll
            for (int i = 0; i < 4; i++) {
                int idx = tid + i * 256, row = idx >> 3, c4 = idx & 7;
                ra[i] = *(const float4*)(A + (size_t)(m0 + row) * lda + k0 + c4 * 4);
            }
            #pragma unroll
            for (int i = 0; i < 2; i++) {
                int idx = tid + i * 256, row = idx >> 3, c4 = idx & 7;
                rb[i] = *(const float4*)(B + (size_t)(n0 + row) * ldb + k0 + c4 * 4);
            }
        }

        #pragma unroll
        for (int ks = 0; ks < 2; ks++) {
            const int kb2 = ks * 32;
            unsigned aH[2][4], aL[2][4], bH[2][4], bL[2][4];
            #pragma unroll
            for (int mi = 0; mi < 2; mi++) {
                LDSM_X4(aH[mi][0], aH[mi][1], aH[mi][2], aH[mi][3], aHb[mi] + kb2);
                LDSM_X4(aL[mi][0], aL[mi][1], aL[mi][2], aL[mi][3], aLb[mi] + kb2);
            }
            #pragma unroll
            for (int nip = 0; nip < 2; nip++) {
                LDSM_X4(bH[nip][0], bH[nip][1], bH[nip][2], bH[nip][3], bHb[nip] + kb2);
                LDSM_X4(bL[nip][0], bL[nip][1], bL[nip][2], bL[nip][3], bLb[nip] + kb2);
            }
            #pragma unroll
            for (int mi = 0; mi < 2; mi++)
                #pragma unroll
                for (int nip = 0; nip < 2; nip++)
                    #pragma unroll
                    for (int hh = 0; hh < 2; hh++) {
                        int ni = nip * 2 + hh;
                        unsigned b0 = bH[nip][hh * 2], b1 = bH[nip][hh * 2 + 1];
                        unsigned l0 = bL[nip][hh * 2], l1 = bL[nip][hh * 2 + 1];
                        MMA_BF16(acc[mi][ni], aH[mi][0], aH[mi][1], aH[mi][2], aH[mi][3], b0, b1);
                        MMA_BF16(acc[mi][ni], aH[mi][0], aH[mi][1], aH[mi][2], aH[mi][3], l0, l1);
                        MMA_BF16(acc[mi][ni], aL[mi][0], aL[mi][1], aL[mi][2], aL[mi][3], b0, b1);
                    }
        }
        __syncthreads();
    }

    #pragma unroll
    for (int mi = 0; mi < 2; mi++)
        #pragma unroll
        for (int ni = 0; ni < 4; ni++) {
            int r = m0 + wm + mi * 16 + gr;
            int c = n0 + wn + ni * 8 + gc * 2;
            float* cc = acc[mi][ni];
            if (MODE == 3) {
                __half* Ch = (__half*)Chv;
                int b = r >> 11, s = r & 2047;
                int h = c >> 6, d = c & 63;
                float b0 = bias[c], b1 = bias[c + 1];
                size_t base = ((size_t)(b * 16 + h) * 64 + d) * 2048;
                Ch[base + s]            = __float2half_rn(cc[0] + b0);
                Ch[base + 2048 + s]     = __float2half_rn(cc[1] + b1);
                Ch[base + s + 8]        = __float2half_rn(cc[2] + b0);
                Ch[base + 2048 + s + 8] = __float2half_rn(cc[3] + b1);
            } else if (MODE == 5) {
                __nv_bfloat16* Ch = (__nv_bfloat16*)Chv;
                __nv_bfloat16* Cl = (__nv_bfloat16*)Clv;
                float b0 = bias[c], b1 = bias[c + 1];
                float v00 = cc[0] + b0, v01 = cc[1] + b1;
                float v10 = cc[2] + b0, v11 = cc[3] + b1;
                float h00 = __bfloat162float(__float2bfloat16_rn(v00));
                float h01 = __bfloat162float(__float2bfloat16_rn(v01));
                float h10 = __bfloat162float(__float2bfloat16_rn(v10));
                float h11 = __bfloat162float(__float2bfloat16_rn(v11));
                size_t o0 = (size_t)r * ldc + c;
                size_t o1 = (size_t)(r + 8) * ldc + c;
                *(unsigned*)&Ch[o0] = pack_bf2(v00, v01);
                *(unsigned*)&Ch[o1] = pack_bf2(v10, v11);
                *(unsigned*)&Cl[o0] = pack_bf2(v00 - h00, v01 - h01);
                *(unsigned*)&Cl[o1] = pack_bf2(v10 - h10, v11 - h11);
            } else {
                float b0 = 0.f, b1 = 0.f;
                if (bias) { b0 = bias[c]; b1 = bias[c + 1]; }
                float2 v0 = make_float2(cc[0] + b0, cc[1] + b1);
                float2 v1 = make_float2(cc[2] + b0, cc[3] + b1);
                *(float2*)&C[(size_t)r * ldc + c]       = v0;
                *(float2*)&C[(size_t)(r + 8) * ldc + c] = v1;
            }
        }
}

// ============================================================================
// Fused scores + softmax + AV. P fragments reused directly from the scores
// accumulators (FA2-style, no smem P round-trip). Each warp's AV covers its
// own 64-k range over the full d=64; the two k-groups' partial O are combined
// once at the end via smem scratch. cp.async double-buffered K/V, 1 sync/iter.
// ============================================================================
#define OQH   0
#define OQL   18432
#define OKH0  36864
#define OKH1  55296
#define OKL0  73728
#define OKL1  92160
#define OVH0  110592
#define OVH1  128000
#define OINV  145408
#define OPSUM 145920
#define FUSED_SMEM 146944
#define KBUF_STRIDE 18432
#define VBUF_STRIDE 17408
#define SAQ 72
#define SAP 136
#define SOC_STRIDE 68   // float stride for O-combine scratch (reuses K region)

__global__ void __launch_bounds__(256, 1)
fused_attn(const __nv_bfloat16* __restrict__ Qh, const __nv_bfloat16* __restrict__ Ql,
           const __nv_bfloat16* __restrict__ Kh, const __nv_bfloat16* __restrict__ Kl,
           const __half* __restrict__ Vh,
           __half* __restrict__ P, float* __restrict__ rinv,
           float* __restrict__ O)
{
    extern __shared__ char sm[];
    __nv_bfloat16* sQH = (__nv_bfloat16*)(sm + OQH);
    __nv_bfloat16* sQL = (__nv_bfloat16*)(sm + OQL);
    float* sInv  = (float*)(sm + OINV);
    float* sPsum = (float*)(sm + OPSUM);

    const unsigned kh0 = smem_u32(sm + OKH0);
    const unsigned kl0 = smem_u32(sm + OKL0);
    const unsigned vh0 = smem_u32(sm + OVH0);

    const int z = blockIdx.z, bb = z >> 4, hh_ = z & 15;
    const int m0 = blockIdx.x * 128;
    const size_t qoff = (size_t)bb * SEQX * D_MODELX + (size_t)hh_ * D_HEADX;
    Qh += qoff; Ql += qoff; Kh += qoff; Kl += qoff;
    Vh += (size_t)z * D_HEADX * SEQX;
    P  += (size_t)z * SEQX * SEQX;
    rinv += (size_t)z * SEQX;
    O  += qoff;

    const int tid  = threadIdx.x;
    const int warp = tid >> 5, lane = tid & 31;
    const int wm = (warp & 3) * 32;
    const int wg = warp >> 2;          // k-group: 0 or 1
    const int wn = wg * 64;            // warp's n (= AV k) base within tile
    const int gr = lane >> 2;
    const int gc = lane & 3;
    const int ti = lane >> 3, ri = lane & 7;

    // ---- load Q tile once ----
    #pragma unroll
    for (int i = 0; i < 4; i++) {
        int idx = tid + i * 256, row = idx >> 3, c8 = idx & 7;
        size_t oa = (size_t)(m0 + row) * D_MODELX + c8 * 8;
        *(uint4*)&sQH[row * SAQ + c8 * 8] = *(const uint4*)(Qh + oa);
        *(uint4*)&sQL[row * SAQ + c8 * 8] = *(const uint4*)(Ql + oa);
    }

    // ---- prefetch K/V tile 0 ----
    {
        #pragma unroll
        for (int i = 0; i < 4; i++) {
            int idx = tid + i * 256, row = idx >> 3, c8 = idx & 7;
            unsigned so = (unsigned)(row * SAQ + c8 * 8) * 2;
            CP_ASYNC16(kh0 + so, Kh + (size_t)row * D_MODELX + c8 * 8);
            CP_ASYNC16(kl0 + so, Kl + (size_t)row * D_MODELX + c8 * 8);
        }
        #pragma unroll
        for (int i = 0; i < 4; i++) {
            int idx = tid + i * 256, row = idx >> 4, c16 = idx & 15;
            unsigned so = (unsigned)(row * SAP + c16 * 8) * 2;
            CP_ASYNC16(vh0 + so, Vh + (size_t)row * SEQX + c16 * 8);
        }
        CP_COMMIT();
    }

    // fragment bases
    unsigned aHb[2], aLb[2], bHb[4], bLb[4], vHb[4];
    #pragma unroll
    for (int mi = 0; mi < 2; mi++) {
        int row = wm + mi * 16 + (ti & 1) * 8 + ri;
        int col = (ti >> 1) * 8;
        aHb[mi] = smem_u32(&sQH[row * SAQ + col]);
        aLb[mi] = smem_u32(&sQL[row * SAQ + col]);
    }
    #pragma unroll
    for (int nip = 0; nip < 4; nip++) {
        int row = wn + (nip * 2 + (ti >> 1)) * 8 + ri;
        int col = (ti & 1) * 8;
        bHb[nip] = kh0 + (unsigned)(row * SAQ + col) * 2;
        bLb[nip] = kl0 + (unsigned)(row * SAQ + col) * 2;
    }
    #pragma unroll
    for (int nip = 0; nip < 4; nip++) {
        int row = (nip * 2 + (ti >> 1)) * 8 + ri;            // d index 0..63
        int col = (ti & 1) * 8 + wn;                          // k within V tile
        vHb[nip] = vh0 + (unsigned)(row * SAP + col) * 2;
    }

    float Oacc[2][8][4] = {};
    float rowsum[4] = {0.f, 0.f, 0.f, 0.f};

    for (int nb = 0; nb < 16; nb++) {
        const int n0 = nb * 128;
        const unsigned kofs = (unsigned)(nb & 1) * KBUF_STRIDE;
        const unsigned vofs = (unsigned)(nb & 1) * VBUF_STRIDE;

        CP_WAIT_ALL();
        __syncthreads();

        if (nb + 1 < 16) {
            const int n1 = n0 + 128;
            const unsigned kn = (unsigned)((nb + 1) & 1) * KBUF_STRIDE;
            const unsigned vn = (unsigned)((nb + 1) & 1) * VBUF_STRIDE;
            #pragma unroll
            for (int i = 0; i < 4; i++) {
                int idx = tid + i * 256, row = idx >> 3, c8 = idx & 7;
                unsigned so = (unsigned)(row * SAQ + c8 * 8) * 2;
                CP_ASYNC16(kh0 + kn + so, Kh + (size_t)(n1 + row) * D_MODELX + c8 * 8);
                CP_ASYNC16(kl0 + kn + so, Kl + (size_t)(n1 + row) * D_MODELX + c8 * 8);
            }
            #pragma unroll
            for (int i = 0; i < 4; i++) {
                int idx = tid + i * 256, row = idx >> 4, c16 = idx & 15;
                unsigned so = (unsigned)(row * SAP + c16 * 8) * 2;
                CP_ASYNC16(vh0 + vn + so, Vh + (size_t)row * SEQX + n1 + c16 * 8);
            }
            CP_COMMIT();
        }

        // ---- scores: S = QK^T, 3-pass bf16 ----
        float acc[2][8][4] = {};
        #pragma unroll
        for (int ks = 0; ks < 4; ks++) {
            const int kb2 = ks * 32;
            unsigned aH[2][4], aL[2][4], bH[4][4], bL[4][4];
            #pragma unroll
            for (int mi = 0; mi < 2; mi++) {
                LDSM_X4(aH[mi][0], aH[mi][1], aH[mi][2], aH[mi][3], aHb[mi] + kb2);
                LDSM_X4(aL[mi][0], aL[mi][1], aL[mi][2], aL[mi][3], aLb[mi] + kb2);
            }
            #pragma unroll
            for (int nip = 0; nip < 4; nip++) {
                LDSM_X4(bH[nip][0], bH[nip][1], bH[nip][2], bH[nip][3], bHb[nip] + kofs + kb2);
                LDSM_X4(bL[nip][0], bL[nip][1], bL[nip][2], bL[nip][3], bLb[nip] + kofs + kb2);
            }
            #pragma unroll
            for (int nip = 0; nip < 4; nip++)
                #pragma unroll
                for (int hh = 0; hh < 2; hh++) {
                    int ni = nip * 2 + hh;
                    unsigned b0 = bH[nip][hh * 2], b1 = bH[nip][hh * 2 + 1];
                    unsigned l0 = bL[nip][hh * 2], l1 = bL[nip][hh * 2 + 1];
                    #pragma unroll
                    for (int mi = 0; mi < 2; mi++) {
                        MMA_BF16(acc[mi][ni], aH[mi][0], aH[mi][1], aH[mi][2], aH[mi][3], b0, b1);
                        MMA_BF16(acc[mi][ni], aH[mi][0], aH[mi][1], aH[mi][2], aH[mi][3], l0, l1);
                        MMA_BF16(acc[mi][ni], aL[mi][0], aL[mi][1], aL[mi][2], aL[mi][3], b0, b1);
                    }
                }
        }

        // ---- exp -> gmem P + repack into acc registers as A fragments ----
        #pragma unroll
        for (int mi = 0; mi < 2; mi++)
            #pragma unroll
            for (int ni = 0; ni < 8; ni++) {
                int rl = wm + mi * 16 + gr;
                int c  = wn + ni * 8 + gc * 2;
                float* cc = acc[mi][ni];
                float e0 = __expf(cc[0] * 0.125f);
                float e1 = __expf(cc[1] * 0.125f);
                float e2 = __expf(cc[2] * 0.125f);
                float e3 = __expf(cc[3] * 0.125f);
                __half2 h0 = __floats2half2_rn(e0, e1);
                __half2 h1 = __floats2half2_rn(e2, e3);
                __stcs((int*)&P[(size_t)(m0 + rl) * SEQX + n0 + c], *(int*)&h0);
                __stcs((int*)&P[(size_t)(m0 + rl + 8) * SEQX + n0 + c], *(int*)&h1);
                rowsum[mi * 2]     += e0 + e1;
                rowsum[mi * 2 + 1] += e2 + e3;
                *(unsigned*)&cc[0] = *(unsigned*)&h0;   // a0/a2 slot
                *(unsigned*)&cc[1] = *(unsigned*)&h1;   // a1/a3 slot
            }

        // ---- AV: Oacc += P(frag regs) @ Vtile^T over this warp's 64 k's ----
        #pragma unroll
        for (int ks2 = 0; ks2 < 4; ks2++) {
            const int kb2 = ks2 * 32;
            unsigned vH[4][4];
            #pragma unroll
            for (int nip = 0; nip < 4; nip++)
                LDSM_X4(vH[nip][0], vH[nip][1], vH[nip][2], vH[nip][3], vHb[nip] + vofs + kb2);
            #pragma unroll
            for (int mi = 0; mi < 2; mi++) {
                unsigned a0 = *(unsigned*)&acc[mi][2 * ks2][0];
                unsigned a1 = *(unsigned*)&acc[mi][2 * ks2][1];
                unsigned a2 = *(unsigned*)&acc[mi][2 * ks2 + 1][0];
                unsigned a3 = *(unsigned*)&acc[mi][2 * ks2 + 1][1];
                #pragma unroll
                for (int nd = 0; nd < 8; nd++)
                    MMA_F16(Oacc[mi][nd], a0, a1, a2, a3,
                            vH[nd >> 1][(nd & 1) * 2], vH[nd >> 1][(nd & 1) * 2 + 1]);
            }
        }
    }

    // ---- finalize rowsum (combine the two k-groups) ----
    #pragma unroll
    for (int j = 0; j < 4; j++) {
        rowsum[j] += __shfl_xor_sync(0xffffffffu, rowsum[j], 1);
        rowsum[j] += __shfl_xor_sync(0xffffffffu, rowsum[j], 2);
    }
    if (gc == 0) {
        sPsum[wg * 128 + wm + gr]      = rowsum[0];
        sPsum[wg * 128 + wm + 8 + gr]  = rowsum[1];
        sPsum[wg * 128 + wm + 16 + gr] = rowsum[2];
        sPsum[wg * 128 + wm + 24 + gr] = rowsum[3];
    }
    __syncthreads();
    if (tid < 128) {
        float inv = 1.0f / (sPsum[tid] + sPsum[128 + tid]);
        sInv[tid] = inv;
        rinv[m0 + tid] = inv;
    }
    __syncthreads();

    // ---- combine k-group partial O via smem scratch (reuse K region) ----
    float* sOc = (float*)(sm + OKH0);   // 128 x SOC_STRIDE floats = 34816 B
    if (wg == 1) {
        #pragma unroll
        for (int mi = 0; mi < 2; mi++)
            #pragma unroll
            for (int nd = 0; nd < 8; nd++) {
                int rl = wm + mi * 16 + gr;
                int c  = nd * 8 + gc * 2;
                float* cc = Oacc[mi][nd];
                sOc[rl * SOC_STRIDE + c]           = cc[0];
                sOc[rl * SOC_STRIDE + c + 1]       = cc[1];
                sOc[(rl + 8) * SOC_STRIDE + c]     = cc[2];
                sOc[(rl + 8) * SOC_STRIDE + c + 1] = cc[3];
            }
    }
    __syncthreads();
    if (wg == 0) {
        #pragma unroll
        for (int mi = 0; mi < 2; mi++)
            #pragma unroll
            for (int nd = 0; nd < 8; nd++) {
                int rl = wm + mi * 16 + gr;
                int c  = nd * 8 + gc * 2;
                float inv0 = sInv[rl], inv1 = sInv[rl + 8];
                float* cc = Oacc[mi][nd];
                float o00 = (cc[0] + sOc[rl * SOC_STRIDE + c])           * inv0;
                float o01 = (cc[1] + sOc[rl * SOC_STRIDE + c + 1])       * inv0;
                float o10 = (cc[2] + sOc[(rl + 8) * SOC_STRIDE + c])     * inv1;
                float o11 = (cc[3] + sOc[(rl + 8) * SOC_STRIDE + c + 1]) * inv1;
                *(float2*)&O[(size_t)(m0 + rl) * D_MODELX + c]     = make_float2(o00, o01);
                *(float2*)&O[(size_t)(m0 + rl + 8) * D_MODELX + c] = make_float2(o10, o11);
            }
    }
}

// ============================================================================
// avg: barrier-free head average.
// ============================================================================
__global__ __launch_bounds__(256)
void avg_kernel(const __half* __restrict__ P, const float* __restrict__ rinv,
                float* __restrict__ avg)
{
    const int bq = blockIdx.x;
    const int t  = threadIdx.x;
    const int b  = bq >> 11;
    const int q  = bq & 2047;

    float acc[8] = {};

    #pragma unroll 8
    for (int h = 0; h < NUM_HEADSX; ++h) {
        const int z = b * 16 + h;
        float inv = rinv[(size_t)z * SEQX + q];
        const uint4* p4 = (const uint4*)(P + ((size_t)z * SEQX + q) * SEQX);
        uint4 u = __ldcs(p4 + t);
        float2 v0 = __half22float2(*reinterpret_cast<__half2*>(&u.x));
        float2 v1 = __half22float2(*reinterpret_cast<__half2*>(&u.y));
        float2 v2 = __half22float2(*reinterpret_cast<__half2*>(&u.z));
        float2 v3 = __half22float2(*reinterpret_cast<__half2*>(&u.w));
        acc[0] += v0.x * inv; acc[1] += v0.y * inv;
        acc[2] += v1.x * inv; acc[3] += v1.y * inv;
        acc[4] += v2.x * inv; acc[5] += v2.y * inv;
        acc[6] += v3.x * inv; acc[7] += v3.y * inv;
    }

    float* a = avg + (size_t)bq * SEQX + t * 8;
    float4 o0 = make_float4(acc[0] * (1.0f / NUM_HEADSX), acc[1] * (1.0f / NUM_HEADSX),
                            acc[2] * (1.0f / NUM_HEADSX), acc[3] * (1.0f / NUM_HEADSX));
    float4 o1 = make_float4(acc[4] * (1.0f / NUM_HEADSX), acc[5] * (1.0f / NUM_HEADSX),
                            acc[6] * (1.0f / NUM_HEADSX), acc[7] * (1.0f / NUM_HEADSX));
    __stcs((float4*)a, o0);
    __stcs((float4*)(a + 4), o1);
}

// ============================================================================
// launch
// ============================================================================
extern "C" void kernel_launch(void* const* d_in, const int* in_sizes, int n_in,
                              void* d_out, int out_size)
{
    const float* x_q = (const float*)d_in[0];
    const float* x_k = (const float*)d_in[1];
    const float* x_v = (const float*)d_in[2];
    const float* Wq  = (const float*)d_in[3];
    const float* bq  = (const float*)d_in[4];
    const float* Wk  = (const float*)d_in[5];
    const float* bk  = (const float*)d_in[6];
    const float* Wv  = (const float*)d_in[7];
    const float* bv  = (const float*)d_in[8];
    const float* Wo  = (const float*)d_in[9];
    const float* bo  = (const float*)d_in[10];

    float* out = (float*)d_out;
    float* avg = out + (size_t)M_TOK * D_MODELX;

    __nv_bfloat16 *Qh, *Ql, *Kh, *Kl;
    __half *Vth, *P;
    float *gO, *rinv;
    cudaGetSymbolAddress((void**)&Qh, g_Qh);
    cudaGetSymbolAddress((void**)&Ql, g_Ql);
    cudaGetSymbolAddress((void**)&Kh, g_Kh);
    cudaGetSymbolAddress((void**)&Kl, g_Kl);
    cudaGetSymbolAddress((void**)&Vth, g_Vth);
    cudaGetSymbolAddress((void**)&gO, g_O);
    cudaGetSymbolAddress((void**)&P, g_P);
    cudaGetSymbolAddress((void**)&rinv, g_rinv);

    cudaFuncSetAttribute(fused_attn, cudaFuncAttributeMaxDynamicSharedMemorySize,
                         FUSED_SMEM);

    dim3 blk(256);
    dim3 gproj(D_MODELX / 64, M_TOK / 128, 1);   // (16, 64)

    // 1-3) projections
    mma_gemm<5><<<gproj, blk>>>(x_q, Wq, nullptr, Qh, Ql,
                                D_MODELX, D_MODELX, D_MODELX, D_MODELX, bq);
    mma_gemm<5><<<gproj, blk>>>(x_k, Wk, nullptr, Kh, Kl,
                                D_MODELX, D_MODELX, D_MODELX, D_MODELX, bk);
    mma_gemm<3><<<gproj, blk>>>(x_v, Wv, nullptr, Vth, nullptr,
                                D_MODELX, D_MODELX, 0, D_MODELX, bv);

    // 4) fused scores + softmax + AV (register-resident P)
    dim3 gf(SEQX / 128, 1, NZ);                  // (16, 1, 64)
    fused_attn<<<gf, blk, FUSED_SMEM>>>(Qh, Ql, Kh, Kl, Vth, P, rinv, gO);

    // 5) head-average
    avg_kernel<<<M_TOK, blk>>>(P, rinv, avg);

    // 6) output projection
    mma_gemm<0><<<gproj, blk>>>(gO, Wo, out, nullptr, nullptr,
                                D_MODELX, D_MODELX, D_MODELX, D_MODELX, bo);
}

// round 17
// speedup vs baseline: 1.2488x; 1.0369x over previous
#include <cuda_runtime.h>
#include <cuda_bf16.h>
#include <cuda_fp16.h>
#include <cstdint>

#define D_MODELX 1024
#define NUM_HEADSX 16
#define D_HEADX 64
#define BATCHX 4
#define SEQX 2048
#define M_TOK (BATCHX * SEQX)    // 8192
#define NZ (BATCHX * NUM_HEADSX) // 64

// ---- static device scratch ----
__device__ __nv_bfloat16 g_Qh[(size_t)M_TOK * D_MODELX];
__device__ __nv_bfloat16 g_Ql[(size_t)M_TOK * D_MODELX];
__device__ __nv_bfloat16 g_Kh[(size_t)M_TOK * D_MODELX];
__device__ __nv_bfloat16 g_Kl[(size_t)M_TOK * D_MODELX];
__device__ __half g_Vth[(size_t)M_TOK * D_MODELX];  // [Z][64][2048] fp16
__device__ float  g_O[(size_t)M_TOK * D_MODELX];
__device__ __half g_P[(size_t)NZ * SEQX * SEQX];    // 0.5 GiB fp16 exp(scores)
__device__ float  g_rinv[(size_t)NZ * SEQX];

__device__ __forceinline__ unsigned pack_bf2(float x, float y) {
    __nv_bfloat162 t = __floats2bfloat162_rn(x, y);
    return *reinterpret_cast<unsigned*>(&t);
}

__device__ __forceinline__ unsigned smem_u32(const void* p) {
    return (unsigned)__cvta_generic_to_shared(p);
}

#define LDSM_X4(r0, r1, r2, r3, addr)                                         \
    asm volatile("ldmatrix.sync.aligned.m8n8.x4.shared.b16 {%0,%1,%2,%3}, [%4];" \
        : "=r"(r0), "=r"(r1), "=r"(r2), "=r"(r3) : "r"(addr))

#define MMA_BF16(c, a0, a1, a2, a3, b0, b1)                                   \
    asm volatile(                                                             \
        "mma.sync.aligned.m16n8k16.row.col.f32.bf16.bf16.f32 "                \
        "{%0,%1,%2,%3},{%4,%5,%6,%7},{%8,%9},{%0,%1,%2,%3};"                  \
        : "+f"(c[0]), "+f"(c[1]), "+f"(c[2]), "+f"(c[3])                      \
        : "r"(a0), "r"(a1), "r"(a2), "r"(a3), "r"(b0), "r"(b1))

#define MMA_F16(c, a0, a1, a2, a3, b0, b1)                                    \
    asm volatile(                                                             \
        "mma.sync.aligned.m16n8k16.row.col.f32.f16.f16.f32 "                  \
        "{%0,%1,%2,%3},{%4,%5,%6,%7},{%8,%9},{%0,%1,%2,%3};"                  \
        : "+f"(c[0]), "+f"(c[1]), "+f"(c[2]), "+f"(c[3])                      \
        : "r"(a0), "r"(a1), "r"(a2), "r"(a3), "r"(b0), "r"(b1))

#define CP_ASYNC16(dst, src)                                                  \
    asm volatile("cp.async.cg.shared.global [%0], [%1], 16;"                  \
        :: "r"(dst), "l"(src) : "memory")
#define CP_COMMIT() asm volatile("cp.async.commit_group;" ::: "memory")
#define CP_WAIT_ALL() asm volatile("cp.async.wait_group 0;" ::: "memory")

// ============================================================================
// NT bf16-split MMA GEMM (fp32 in, split in-kernel): C = A @ B^T + bias
// MODE 0: fp32 out + bias; MODE 3: V proj transposed fp16 (hi only);
// MODE 5: Q/K proj bf16 hi/lo + bias.  128x64x32, 256 threads.
// ============================================================================
template <int MODE>
__global__ __launch_bounds__(256)
void mma_gemm(const float* __restrict__ A,
              const float* __restrict__ B,
              float* __restrict__ C,
              void* __restrict__ Chv, void* __restrict__ Clv,
              int lda, int ldb, int ldc,
              int K, const float* __restrict__ bias)
{
    constexpr int BM = 128, BN = 64, BK = 32;
    constexpr int SA = 40;

    __shared__ __align__(16) __nv_bfloat16 AsH[BM * SA];
    __shared__ __align__(16) __nv_bfloat16 AsL[BM * SA];
    __shared__ __align__(16) __nv_bfloat16 BsH[BN * SA];
    __shared__ __align__(16) __nv_bfloat16 BsL[BN * SA];

    const int tid  = threadIdx.x;
    const int m0   = blockIdx.y * BM;
    const int n0   = blockIdx.x * BN;
    const int warp = tid >> 5, lane = tid & 31;
    const int wm = (warp & 3) * 32;
    const int wn = (warp >> 2) * 32;
    const int gr = lane >> 2;
    const int gc = lane & 3;
    const int ti = lane >> 3, ri = lane & 7;

    unsigned aHb[2], aLb[2], bHb[2], bLb[2];
    #pragma unroll
    for (int mi = 0; mi < 2; mi++) {
        int row = wm + mi * 16 + (ti & 1) * 8 + ri;
        int col = (ti >> 1) * 8;
        aHb[mi] = smem_u32(&AsH[row * SA + col]);
        aLb[mi] = smem_u32(&AsL[row * SA + col]);
    }
    #pragma unroll
    for (int nip = 0; nip < 2; nip++) {
        int row = wn + (nip * 2 + (ti >> 1)) * 8 + ri;
        int col = (ti & 1) * 8;
        bHb[nip] = smem_u32(&BsH[row * SA + col]);
        bLb[nip] = smem_u32(&BsL[row * SA + col]);
    }

    float acc[2][4][4] = {};
    float4 ra[4], rb[2];

    {
        #pragma unroll
        for (int i = 0; i < 4; i++) {
            int idx = tid + i * 256, row = idx >> 3, c4 = idx & 7;
            ra[i] = *(const float4*)(A + (size_t)(m0 + row) * lda + c4 * 4);
        }
        #pragma unroll
        for (int i = 0; i < 2; i++) {
            int idx = tid + i * 256, row = idx >> 3, c4 = idx & 7;
            rb[i] = *(const float4*)(B + (size_t)(n0 + row) * ldb + c4 * 4);
        }
    }

    const int niter = K / BK;
    for (int it = 0; it < niter; ++it) {
        #pragma unroll
        for (int i = 0; i < 4; i++) {
            int idx = tid + i * 256, row = idx >> 3, c4 = idx & 7;
            float v0 = ra[i].x, v1 = ra[i].y, v2 = ra[i].z, v3 = ra[i].w;
            float h0 = __bfloat162float(__float2bfloat16_rn(v0));
            float h1 = __bfloat162float(__float2bfloat16_rn(v1));
            float h2 = __bfloat162float(__float2bfloat16_rn(v2));
            float h3 = __bfloat162float(__float2bfloat16_rn(v3));
            uint2 H, L;
            H.x = pack_bf2(v0, v1); H.y = pack_bf2(v2, v3);
            L.x = pack_bf2(v0 - h0, v1 - h1); L.y = pack_bf2(v2 - h2, v3 - h3);
            *(uint2*)&AsH[row * SA + c4 * 4] = H;
            *(uint2*)&AsL[row * SA + c4 * 4] = L;
        }
        #pragma unroll
        for (int i = 0; i < 2; i++) {
            int idx = tid + i * 256, row = idx >> 3, c4 = idx & 7;
            float v0 = rb[i].x, v1 = rb[i].y, v2 = rb[i].z, v3 = rb[i].w;
            float h0 = __bfloat162float(__float2bfloat16_rn(v0));
            float h1 = __bfloat162float(__float2bfloat16_rn(v1));
            float h2 = __bfloat162float(__float2bfloat16_rn(v2));
            float h3 = __bfloat162float(__float2bfloat16_rn(v3));
            uint2 H, L;
            H.x = pack_bf2(v0, v1); H.y = pack_bf2(v2, v3);
            L.x = pack_bf2(v0 - h0, v1 - h1); L.y = pack_bf2(v2 - h2, v3 - h3);
            *(uint2*)&BsH[row * SA + c4 * 4] = H;
            *(uint2*)&BsL[row * SA + c4 * 4] = L;
        }
        __syncthreads();

        if (it + 1 < niter) {
            int k0 = (it + 1) * BK;
            #pragma unroll
            for (int i = 0; i < 4; i++) {
                int idx = tid + i * 256, row = idx >> 3, c4 = idx & 7;
                ra[i] = *(const float4*)(A + (size_t)(m0 + row) * lda + k0 + c4 * 4);
            }
            #pragma unroll
            for (int i = 0; i < 2; i++) {
                int idx = tid + i * 256, row = idx >> 3, c4 = idx & 7;
                rb[i] = *(const float4*)(B + (size_t)(n0 + row) * ldb + k0 + c4 * 4);
            }
        }

        #pragma unroll
        for (int ks = 0; ks < 2; ks++) {
            const int kb2 = ks * 32;
            unsigned aH[2][4], aL[2][4], bH[2][4], bL[2][4];
            #pragma unroll
            for (int mi = 0; mi < 2; mi++) {
                LDSM_X4(aH[mi][0], aH[mi][1], aH[mi][2], aH[mi][3], aHb[mi] + kb2);
                LDSM_X4(aL[mi][0], aL[mi][1], aL[mi][2], aL[mi][3], aLb[mi] + kb2);
            }
            #pragma unroll
            for (int nip = 0; nip < 2; nip++) {
                LDSM_X4(bH[nip][0], bH[nip][1], bH[nip][2], bH[nip][3], bHb[nip] + kb2);
                LDSM_X4(bL[nip][0], bL[nip][1], bL[nip][2], bL[nip][3], bLb[nip] + kb2);
            }
            #pragma unroll
            for (int mi = 0; mi < 2; mi++)
                #pragma unroll
                for (int nip = 0; nip < 2; nip++)
                    #pragma unroll
                    for (int hh = 0; hh < 2; hh++) {
                        int ni = nip * 2 + hh;
                        unsigned b0 = bH[nip][hh * 2], b1 = bH[nip][hh * 2 + 1];
                        unsigned l0 = bL[nip][hh * 2], l1 = bL[nip][hh * 2 + 1];
                        MMA_BF16(acc[mi][ni], aH[mi][0], aH[mi][1], aH[mi][2], aH[mi][3], b0, b1);
                        MMA_BF16(acc[mi][ni], aH[mi][0], aH[mi][1], aH[mi][2], aH[mi][3], l0, l1);
                        MMA_BF16(acc[mi][ni], aL[mi][0], aL[mi][1], aL[mi][2], aL[mi][3], b0, b1);
                    }
        }
        __syncthreads();
    }

    #pragma unroll
    for (int mi = 0; mi < 2; mi++)
        #pragma unroll
        for (int ni = 0; ni < 4; ni++) {
            int r = m0 + wm + mi * 16 + gr;
            int c = n0 + wn + ni * 8 + gc * 2;
            float* cc = acc[mi][ni];
            if (MODE == 3) {
                __half* Ch = (__half*)Chv;
                int b = r >> 11, s = r & 2047;
                int h = c >> 6, d = c & 63;
                float b0 = bias[c], b1 = bias[c + 1];
                size_t base = ((size_t)(b * 16 + h) * 64 + d) * 2048;
                Ch[base + s]            = __float2half_rn(cc[0] + b0);
                Ch[base + 2048 + s]     = __float2half_rn(cc[1] + b1);
                Ch[base + s + 8]        = __float2half_rn(cc[2] + b0);
                Ch[base + 2048 + s + 8] = __float2half_rn(cc[3] + b1);
            } else if (MODE == 5) {
                __nv_bfloat16* Ch = (__nv_bfloat16*)Chv;
                __nv_bfloat16* Cl = (__nv_bfloat16*)Clv;
                float b0 = bias[c], b1 = bias[c + 1];
                float v00 = cc[0] + b0, v01 = cc[1] + b1;
                float v10 = cc[2] + b0, v11 = cc[3] + b1;
                float h00 = __bfloat162float(__float2bfloat16_rn(v00));
                float h01 = __bfloat162float(__float2bfloat16_rn(v01));
                float h10 = __bfloat162float(__float2bfloat16_rn(v10));
                float h11 = __bfloat162float(__float2bfloat16_rn(v11));
                size_t o0 = (size_t)r * ldc + c;
                size_t o1 = (size_t)(r + 8) * ldc + c;
                *(unsigned*)&Ch[o0] = pack_bf2(v00, v01);
                *(unsigned*)&Ch[o1] = pack_bf2(v10, v11);
                *(unsigned*)&Cl[o0] = pack_bf2(v00 - h00, v01 - h01);
                *(unsigned*)&Cl[o1] = pack_bf2(v10 - h10, v11 - h11);
            } else {
                float b0 = 0.f, b1 = 0.f;
                if (bias) { b0 = bias[c]; b1 = bias[c + 1]; }
                float2 v0 = make_float2(cc[0] + b0, cc[1] + b1);
                float2 v1 = make_float2(cc[2] + b0, cc[3] + b1);
                *(float2*)&C[(size_t)r * ldc + c]       = v0;
                *(float2*)&C[(size_t)(r + 8) * ldc + c] = v1;
            }
        }
}

// ============================================================================
// Fused scores + softmax + AV (register-resident P, cp.async K/V) — R16.
// ============================================================================
#define OQH   0
#define OQL   18432
#define OKH0  36864
#define OKH1  55296
#define OKL0  73728
#define OKL1  92160
#define OVH0  110592
#define OVH1  128000
#define OINV  145408
#define OPSUM 145920
#define FUSED_SMEM 146944
#define KBUF_STRIDE 18432
#define VBUF_STRIDE 17408
#define SAQ 72
#define SAP 136
#define SOC_STRIDE 68

__global__ void __launch_bounds__(256, 1)
fused_attn(const __nv_bfloat16* __restrict__ Qh, const __nv_bfloat16* __restrict__ Ql,
           const __nv_bfloat16* __restrict__ Kh, const __nv_bfloat16* __restrict__ Kl,
           const __half* __restrict__ Vh,
           __half* __restrict__ P, float* __restrict__ rinv,
           float* __restrict__ O)
{
    extern __shared__ char sm[];
    __nv_bfloat16* sQH = (__nv_bfloat16*)(sm + OQH);
    __nv_bfloat16* sQL = (__nv_bfloat16*)(sm + OQL);
    float* sInv  = (float*)(sm + OINV);
    float* sPsum = (float*)(sm + OPSUM);

    const unsigned kh0 = smem_u32(sm + OKH0);
    const unsigned kl0 = smem_u32(sm + OKL0);
    const unsigned vh0 = smem_u32(sm + OVH0);

    const int z = blockIdx.z, bb = z >> 4, hh_ = z & 15;
    const int m0 = blockIdx.x * 128;
    const size_t qoff = (size_t)bb * SEQX * D_MODELX + (size_t)hh_ * D_HEADX;
    Qh += qoff; Ql += qoff; Kh += qoff; Kl += qoff;
    Vh += (size_t)z * D_HEADX * SEQX;
    P  += (size_t)z * SEQX * SEQX;
    rinv += (size_t)z * SEQX;
    O  += qoff;

    const int tid  = threadIdx.x;
    const int warp = tid >> 5, lane = tid & 31;
    const int wm = (warp & 3) * 32;
    const int wg = warp >> 2;
    const int wn = wg * 64;
    const int gr = lane >> 2;
    const int gc = lane & 3;
    const int ti = lane >> 3, ri = lane & 7;

    #pragma unroll
    for (int i = 0; i < 4; i++) {
        int idx = tid + i * 256, row = idx >> 3, c8 = idx & 7;
        size_t oa = (size_t)(m0 + row) * D_MODELX + c8 * 8;
        *(uint4*)&sQH[row * SAQ + c8 * 8] = *(const uint4*)(Qh + oa);
        *(uint4*)&sQL[row * SAQ + c8 * 8] = *(const uint4*)(Ql + oa);
    }

    {
        #pragma unroll
        for (int i = 0; i < 4; i++) {
            int idx = tid + i * 256, row = idx >> 3, c8 = idx & 7;
            unsigned so = (unsigned)(row * SAQ + c8 * 8) * 2;
            CP_ASYNC16(kh0 + so, Kh + (size_t)row * D_MODELX + c8 * 8);
            CP_ASYNC16(kl0 + so, Kl + (size_t)row * D_MODELX + c8 * 8);
        }
        #pragma unroll
        for (int i = 0; i < 4; i++) {
            int idx = tid + i * 256, row = idx >> 4, c16 = idx & 15;
            unsigned so = (unsigned)(row * SAP + c16 * 8) * 2;
            CP_ASYNC16(vh0 + so, Vh + (size_t)row * SEQX + c16 * 8);
        }
        CP_COMMIT();
    }

    unsigned aHb[2], aLb[2], bHb[4], bLb[4], vHb[4];
    #pragma unroll
    for (int mi = 0; mi < 2; mi++) {
        int row = wm + mi * 16 + (ti & 1) * 8 + ri;
        int col = (ti >> 1) * 8;
        aHb[mi] = smem_u32(&sQH[row * SAQ + col]);
        aLb[mi] = smem_u32(&sQL[row * SAQ + col]);
    }
    #pragma unroll
    for (int nip = 0; nip < 4; nip++) {
        int row = wn + (nip * 2 + (ti >> 1)) * 8 + ri;
        int col = (ti & 1) * 8;
        bHb[nip] = kh0 + (unsigned)(row * SAQ + col) * 2;
        bLb[nip] = kl0 + (unsigned)(row * SAQ + col) * 2;
    }
    #pragma unroll
    for (int nip = 0; nip < 4; nip++) {
        int row = (nip * 2 + (ti >> 1)) * 8 + ri;
        int col = (ti & 1) * 8 + wn;
        vHb[nip] = vh0 + (unsigned)(row * SAP + col) * 2;
    }

    float Oacc[2][8][4] = {};
    float rowsum[4] = {0.f, 0.f, 0.f, 0.f};

    for (int nb = 0; nb < 16; nb++) {
        const int n0 = nb * 128;
        const unsigned kofs = (unsigned)(nb & 1) * KBUF_STRIDE;
        const unsigned vofs = (unsigned)(nb & 1) * VBUF_STRIDE;

        CP_WAIT_ALL();
        __syncthreads();

        if (nb + 1 < 16) {
            const int n1 = n0 + 128;
            const unsigned kn = (unsigned)((nb + 1) & 1) * KBUF_STRIDE;
            const unsigned vn = (unsigned)((nb + 1) & 1) * VBUF_STRIDE;
            #pragma unroll
            for (int i = 0; i < 4; i++) {
                int idx = tid + i * 256, row = idx >> 3, c8 = idx & 7;
                unsigned so = (unsigned)(row * SAQ + c8 * 8) * 2;
                CP_ASYNC16(kh0 + kn + so, Kh + (size_t)(n1 + row) * D_MODELX + c8 * 8);
                CP_ASYNC16(kl0 + kn + so, Kl + (size_t)(n1 + row) * D_MODELX + c8 * 8);
            }
            #pragma unroll
            for (int i = 0; i < 4; i++) {
                int idx = tid + i * 256, row = idx >> 4, c16 = idx & 15;
                unsigned so = (unsigned)(row * SAP + c16 * 8) * 2;
                CP_ASYNC16(vh0 + vn + so, Vh + (size_t)row * SEQX + n1 + c16 * 8);
            }
            CP_COMMIT();
        }

        float acc[2][8][4] = {};
        #pragma unroll
        for (int ks = 0; ks < 4; ks++) {
            const int kb2 = ks * 32;
            unsigned aH[2][4], aL[2][4], bH[4][4], bL[4][4];
            #pragma unroll
            for (int mi = 0; mi < 2; mi++) {
                LDSM_X4(aH[mi][0], aH[mi][1], aH[mi][2], aH[mi][3], aHb[mi] + kb2);
                LDSM_X4(aL[mi][0], aL[mi][1], aL[mi][2], aL[mi][3], aLb[mi] + kb2);
            }
            #pragma unroll
            for (int nip = 0; nip < 4; nip++) {
                LDSM_X4(bH[nip][0], bH[nip][1], bH[nip][2], bH[nip][3], bHb[nip] + kofs + kb2);
                LDSM_X4(bL[nip][0], bL[nip][1], bL[nip][2], bL[nip][3], bLb[nip] + kofs + kb2);
            }
            #pragma unroll
            for (int nip = 0; nip < 4; nip++)
                #pragma unroll
                for (int hh = 0; hh < 2; hh++) {
                    int ni = nip * 2 + hh;
                    unsigned b0 = bH[nip][hh * 2], b1 = bH[nip][hh * 2 + 1];
                    unsigned l0 = bL[nip][hh * 2], l1 = bL[nip][hh * 2 + 1];
                    #pragma unroll
                    for (int mi = 0; mi < 2; mi++) {
                        MMA_BF16(acc[mi][ni], aH[mi][0], aH[mi][1], aH[mi][2], aH[mi][3], b0, b1);
                        MMA_BF16(acc[mi][ni], aH[mi][0], aH[mi][1], aH[mi][2], aH[mi][3], l0, l1);
                        MMA_BF16(acc[mi][ni], aL[mi][0], aL[mi][1], aL[mi][2], aL[mi][3], b0, b1);
                    }
                }
        }

        #pragma unroll
        for (int mi = 0; mi < 2; mi++)
            #pragma unroll
            for (int ni = 0; ni < 8; ni++) {
                int rl = wm + mi * 16 + gr;
                int c  = wn + ni * 8 + gc * 2;
                float* cc = acc[mi][ni];
                float e0 = __expf(cc[0] * 0.125f);
                float e1 = __expf(cc[1] * 0.125f);
                float e2 = __expf(cc[2] * 0.125f);
                float e3 = __expf(cc[3] * 0.125f);
                __half2 h0 = __floats2half2_rn(e0, e1);
                __half2 h1 = __floats2half2_rn(e2, e3);
                __stcs((int*)&P[(size_t)(m0 + rl) * SEQX + n0 + c], *(int*)&h0);
                __stcs((int*)&P[(size_t)(m0 + rl + 8) * SEQX + n0 + c], *(int*)&h1);
                rowsum[mi * 2]     += e0 + e1;
                rowsum[mi * 2 + 1] += e2 + e3;
                *(unsigned*)&cc[0] = *(unsigned*)&h0;
                *(unsigned*)&cc[1] = *(unsigned*)&h1;
            }

        #pragma unroll
        for (int ks2 = 0; ks2 < 4; ks2++) {
            const int kb2 = ks2 * 32;
            unsigned vH[4][4];
            #pragma unroll
            for (int nip = 0; nip < 4; nip++)
                LDSM_X4(vH[nip][0], vH[nip][1], vH[nip][2], vH[nip][3], vHb[nip] + vofs + kb2);
            #pragma unroll
            for (int mi = 0; mi < 2; mi++) {
                unsigned a0 = *(unsigned*)&acc[mi][2 * ks2][0];
                unsigned a1 = *(unsigned*)&acc[mi][2 * ks2][1];
                unsigned a2 = *(unsigned*)&acc[mi][2 * ks2 + 1][0];
                unsigned a3 = *(unsigned*)&acc[mi][2 * ks2 + 1][1];
                #pragma unroll
                for (int nd = 0; nd < 8; nd++)
                    MMA_F16(Oacc[mi][nd], a0, a1, a2, a3,
                            vH[nd >> 1][(nd & 1) * 2], vH[nd >> 1][(nd & 1) * 2 + 1]);
            }
        }
    }

    #pragma unroll
    for (int j = 0; j < 4; j++) {
        rowsum[j] += __shfl_xor_sync(0xffffffffu, rowsum[j], 1);
        rowsum[j] += __shfl_xor_sync(0xffffffffu, rowsum[j], 2);
    }
    if (gc == 0) {
        sPsum[wg * 128 + wm + gr]      = rowsum[0];
        sPsum[wg * 128 + wm + 8 + gr]  = rowsum[1];
        sPsum[wg * 128 + wm + 16 + gr] = rowsum[2];
        sPsum[wg * 128 + wm + 24 + gr] = rowsum[3];
    }
    __syncthreads();
    if (tid < 128) {
        float inv = 1.0f / (sPsum[tid] + sPsum[128 + tid]);
        sInv[tid] = inv;
        rinv[m0 + tid] = inv;
    }
    __syncthreads();

    float* sOc = (float*)(sm + OKH0);
    if (wg == 1) {
        #pragma unroll
        for (int mi = 0; mi < 2; mi++)
            #pragma unroll
            for (int nd = 0; nd < 8; nd++) {
                int rl = wm + mi * 16 + gr;
                int c  = nd * 8 + gc * 2;
                float* cc = Oacc[mi][nd];
                sOc[rl * SOC_STRIDE + c]           = cc[0];
                sOc[rl * SOC_STRIDE + c + 1]       = cc[1];
                sOc[(rl + 8) * SOC_STRIDE + c]     = cc[2];
                sOc[(rl + 8) * SOC_STRIDE + c + 1] = cc[3];
            }
    }
    __syncthreads();
    if (wg == 0) {
        #pragma unroll
        for (int mi = 0; mi < 2; mi++)
            #pragma unroll
            for (int nd = 0; nd < 8; nd++) {
                int rl = wm + mi * 16 + gr;
                int c  = nd * 8 + gc * 2;
                float inv0 = sInv[rl], inv1 = sInv[rl + 8];
                float* cc = Oacc[mi][nd];
                float o00 = (cc[0] + sOc[rl * SOC_STRIDE + c])           * inv0;
                float o01 = (cc[1] + sOc[rl * SOC_STRIDE + c + 1])       * inv0;
                float o10 = (cc[2] + sOc[(rl + 8) * SOC_STRIDE + c])     * inv1;
                float o11 = (cc[3] + sOc[(rl + 8) * SOC_STRIDE + c + 1]) * inv1;
                *(float2*)&O[(size_t)(m0 + rl) * D_MODELX + c]     = make_float2(o00, o01);
                *(float2*)&O[(size_t)(m0 + rl + 8) * D_MODELX + c] = make_float2(o10, o11);
            }
    }
}

// ============================================================================
// avg: barrier-free head average.
// ============================================================================
__global__ __launch_bounds__(256)
void avg_kernel(const __half* __restrict__ P, const float* __restrict__ rinv,
                float* __restrict__ avg)
{
    const int bq = blockIdx.x;
    const int t  = threadIdx.x;
    const int b  = bq >> 11;
    const int q  = bq & 2047;

    float acc[8] = {};

    #pragma unroll 8
    for (int h = 0; h < NUM_HEADSX; ++h) {
        const int z = b * 16 + h;
        float inv = rinv[(size_t)z * SEQX + q];
        const uint4* p4 = (const uint4*)(P + ((size_t)z * SEQX + q) * SEQX);
        uint4 u = __ldcs(p4 + t);
        float2 v0 = __half22float2(*reinterpret_cast<__half2*>(&u.x));
        float2 v1 = __half22float2(*reinterpret_cast<__half2*>(&u.y));
        float2 v2 = __half22float2(*reinterpret_cast<__half2*>(&u.z));
        float2 v3 = __half22float2(*reinterpret_cast<__half2*>(&u.w));
        acc[0] += v0.x * inv; acc[1] += v0.y * inv;
        acc[2] += v1.x * inv; acc[3] += v1.y * inv;
        acc[4] += v2.x * inv; acc[5] += v2.y * inv;
        acc[6] += v3.x * inv; acc[7] += v3.y * inv;
    }

    float* a = avg + (size_t)bq * SEQX + t * 8;
    float4 o0 = make_float4(acc[0] * (1.0f / NUM_HEADSX), acc[1] * (1.0f / NUM_HEADSX),
                            acc[2] * (1.0f / NUM_HEADSX), acc[3] * (1.0f / NUM_HEADSX));
    float4 o1 = make_float4(acc[4] * (1.0f / NUM_HEADSX), acc[5] * (1.0f / NUM_HEADSX),
                            acc[6] * (1.0f / NUM_HEADSX), acc[7] * (1.0f / NUM_HEADSX));
    __stcs((float4*)a, o0);
    __stcs((float4*)(a + 4), o1);
}

// ============================================================================
// launch — multi-stream overlap: Q/K/V projections concurrent; avg || out-proj.
// ============================================================================
extern "C" void kernel_launch(void* const* d_in, const int* in_sizes, int n_in,
                              void* d_out, int out_size)
{
    const float* x_q = (const float*)d_in[0];
    const float* x_k = (const float*)d_in[1];
    const float* x_v = (const float*)d_in[2];
    const float* Wq  = (const float*)d_in[3];
    const float* bq  = (const float*)d_in[4];
    const float* Wk  = (const float*)d_in[5];
    const float* bk  = (const float*)d_in[6];
    const float* Wv  = (const float*)d_in[7];
    const float* bv  = (const float*)d_in[8];
    const float* Wo  = (const float*)d_in[9];
    const float* bo  = (const float*)d_in[10];

    float* out = (float*)d_out;
    float* avg = out + (size_t)M_TOK * D_MODELX;

    __nv_bfloat16 *Qh, *Ql, *Kh, *Kl;
    __half *Vth, *P;
    float *gO, *rinv;
    cudaGetSymbolAddress((void**)&Qh, g_Qh);
    cudaGetSymbolAddress((void**)&Ql, g_Ql);
    cudaGetSymbolAddress((void**)&Kh, g_Kh);
    cudaGetSymbolAddress((void**)&Kl, g_Kl);
    cudaGetSymbolAddress((void**)&Vth, g_Vth);
    cudaGetSymbolAddress((void**)&gO, g_O);
    cudaGetSymbolAddress((void**)&P, g_P);
    cudaGetSymbolAddress((void**)&rinv, g_rinv);

    static cudaStream_t s1 = nullptr, s2 = nullptr;
    static cudaEvent_t evRoot = nullptr, ev1 = nullptr, ev2 = nullptr,
                       evF = nullptr, evA = nullptr;
    if (s1 == nullptr) {
        cudaStreamCreateWithFlags(&s1, cudaStreamNonBlocking);
        cudaStreamCreateWithFlags(&s2, cudaStreamNonBlocking);
        cudaEventCreateWithFlags(&evRoot, cudaEventDisableTiming);
        cudaEventCreateWithFlags(&ev1, cudaEventDisableTiming);
        cudaEventCreateWithFlags(&ev2, cudaEventDisableTiming);
        cudaEventCreateWithFlags(&evF, cudaEventDisableTiming);
        cudaEventCreateWithFlags(&evA, cudaEventDisableTiming);
        cudaFuncSetAttribute(fused_attn, cudaFuncAttributeMaxDynamicSharedMemorySize,
                             FUSED_SMEM);
    }

    dim3 blk(256);
    dim3 gproj(D_MODELX / 64, M_TOK / 128, 1);   // (16, 64)

    // ---- fork: Q on main, K on s1, V on s2 ----
    cudaEventRecord(evRoot, 0);
    cudaStreamWaitEvent(s1, evRoot, 0);
    cudaStreamWaitEvent(s2, evRoot, 0);

    mma_gemm<5><<<gproj, blk, 0, 0>>>(x_q, Wq, nullptr, Qh, Ql,
                                      D_MODELX, D_MODELX, D_MODELX, D_MODELX, bq);
    mma_gemm<5><<<gproj, blk, 0, s1>>>(x_k, Wk, nullptr, Kh, Kl,
                                       D_MODELX, D_MODELX, D_MODELX, D_MODELX, bk);
    mma_gemm<3><<<gproj, blk, 0, s2>>>(x_v, Wv, nullptr, Vth, nullptr,
                                       D_MODELX, D_MODELX, 0, D_MODELX, bv);
    cudaEventRecord(ev1, s1);
    cudaEventRecord(ev2, s2);
    cudaStreamWaitEvent(0, ev1, 0);
    cudaStreamWaitEvent(0, ev2, 0);

    // ---- fused scores + softmax + AV ----
    dim3 gf(SEQX / 128, 1, NZ);                  // (16, 1, 64)
    fused_attn<<<gf, blk, FUSED_SMEM, 0>>>(Qh, Ql, Kh, Kl, Vth, P, rinv, gO);

    // ---- fork: avg on s1, out-projection on main ----
    cudaEventRecord(evF, 0);
    cudaStreamWaitEvent(s1, evF, 0);
    avg_kernel<<<M_TOK, blk, 0, s1>>>(P, rinv, avg);
    mma_gemm<0><<<gproj, blk, 0, 0>>>(gO, Wo, out, nullptr, nullptr,
                                      D_MODELX, D_MODELX, D_MODELX, D_MODELX, bo);
    cudaEventRecord(evA, s1);
    cudaStreamWaitEvent(0, evA, 0);
}